// round 9
// baseline (speedup 1.0000x reference)
#include <cuda_runtime.h>
#include <cuda_fp16.h>
#include <cstdint>

#define NTOT 16384
#define EMB  100

// Scratch (device globals — no runtime allocation allowed).
__device__ __half g_h1[NTOT * 256];      // relu(gather@sg_w1+b1), f16
__device__ __half g_h2[NTOT * 256];      // h1@sg_w2+b2, f16
__device__ float  g_feat[4 * NTOT * 256]; // per-group partial col-max (+b3)

// ============================== helpers ==============================
__device__ __forceinline__ uint32_t smem_u32(const void* p) {
    uint32_t a;
    asm("{ .reg .u64 t; cvta.to.shared.u64 t, %1; cvt.u32.u64 %0, t; }"
        : "=r"(a) : "l"(p));
    return a;
}
__device__ __forceinline__ uint32_t pack2(float lo, float hi) {
    __half2 h = __floats2half2_rn(lo, hi);
    return *reinterpret_cast<uint32_t*>(&h);
}
__device__ __forceinline__ void ldsm_x4(uint32_t& r0, uint32_t& r1, uint32_t& r2, uint32_t& r3,
                                        uint32_t addr) {
    asm volatile("ldmatrix.sync.aligned.m8n8.x4.shared.b16 {%0,%1,%2,%3}, [%4];"
                 : "=r"(r0), "=r"(r1), "=r"(r2), "=r"(r3) : "r"(addr));
}
__device__ __forceinline__ void ldsm_x2t(uint32_t& r0, uint32_t& r1, uint32_t addr) {
    asm volatile("ldmatrix.sync.aligned.m8n8.x2.trans.shared.b16 {%0,%1}, [%2];"
                 : "=r"(r0), "=r"(r1) : "r"(addr));
}
__device__ __forceinline__ void ldsm_x4t(uint32_t& r0, uint32_t& r1, uint32_t& r2, uint32_t& r3,
                                         uint32_t addr) {
    asm volatile("ldmatrix.sync.aligned.m8n8.x4.trans.shared.b16 {%0,%1,%2,%3}, [%4];"
                 : "=r"(r0), "=r"(r1), "=r"(r2), "=r"(r3) : "r"(addr));
}
__device__ __forceinline__ void mma16816(float* c, const uint32_t* a, uint32_t b0, uint32_t b1) {
    asm volatile("mma.sync.aligned.m16n8k16.row.col.f32.f16.f16.f32 "
                 "{%0,%1,%2,%3}, {%4,%5,%6,%7}, {%8,%9}, {%0,%1,%2,%3};"
                 : "+f"(c[0]), "+f"(c[1]), "+f"(c[2]), "+f"(c[3])
                 : "r"(a[0]), "r"(a[1]), "r"(a[2]), "r"(a[3]), "r"(b0), "r"(b1));
}
#define NAMED_BAR(id) \
    asm volatile("bar.sync %0, 128;" :: "r"(id) : "memory")

// ============================== PointNet (mma.sync f16) ==============================
// SMEM byte offsets
#define SM_W3   0        /* 128 x 512B  (f16, swizzled)  = 65536 */
#define SM_W2   65536    /* 64  x 256B                    = 16384 */
#define SM_H2   81920    /* 128 x 256B                    = 32768 */
#define SM_H1   114688   /* 128 x 128B                    = 16384 */
#define SM_B2   131072   /* 128 f32 */
#define SM_B3   131584   /* 256 f32 */
#define SM_W1   132608   /* 192 f32 */
#define SM_B1   133376   /* 64  f32 */
#define SM_TOTAL 133632

__global__ __launch_bounds__(512, 1) void pointnet_mma(
    const float* __restrict__ pts,
    const float* __restrict__ w1, const float* __restrict__ b1,
    const float* __restrict__ w2, const float* __restrict__ b2,
    const float* __restrict__ w3, const float* __restrict__ b3,
    float* __restrict__ featp, int ntot)
{
    extern __shared__ char sm[];
    const uint32_t s0 = smem_u32(sm);
    const int tid = threadIdx.x;
    const int wid = tid >> 5, lane = tid & 31;

    // ---- Stage weights (once per block) ----
    for (int i = tid * 8; i < 128 * 256; i += 512 * 8) {
        int k = i >> 8, n = i & 255;
        float4 f0 = *reinterpret_cast<const float4*>(w3 + i);
        float4 f1 = *reinterpret_cast<const float4*>(w3 + i + 4);
        uint4 u = make_uint4(pack2(f0.x, f0.y), pack2(f0.z, f0.w),
                             pack2(f1.x, f1.y), pack2(f1.z, f1.w));
        int ch = (n >> 3) ^ (k & 7);
        *reinterpret_cast<uint4*>(sm + SM_W3 + k * 512 + ch * 16) = u;
    }
    for (int i = tid * 8; i < 64 * 128; i += 512 * 8) {
        int k = i >> 7, n = i & 127;
        float4 f0 = *reinterpret_cast<const float4*>(w2 + i);
        float4 f1 = *reinterpret_cast<const float4*>(w2 + i + 4);
        uint4 u = make_uint4(pack2(f0.x, f0.y), pack2(f0.z, f0.w),
                             pack2(f1.x, f1.y), pack2(f1.z, f1.w));
        int ch = (n >> 3) ^ (k & 7);
        *reinterpret_cast<uint4*>(sm + SM_W2 + k * 256 + ch * 16) = u;
    }
    if (tid < 128) reinterpret_cast<float*>(sm + SM_B2)[tid] = b2[tid];
    if (tid < 256) reinterpret_cast<float*>(sm + SM_B3)[tid] = b3[tid];
    if (tid < 192) reinterpret_cast<float*>(sm + SM_W1)[tid] = w1[tid];
    if (tid < 64)  reinterpret_cast<float*>(sm + SM_B1)[tid] = b1[tid];
    __syncthreads();   // only block-wide sync in the whole kernel

    const float* sW1f = reinterpret_cast<const float*>(sm + SM_W1);
    const float* sB1f = reinterpret_cast<const float*>(sm + SM_B1);
    const float* sB2f = reinterpret_cast<const float*>(sm + SM_B2);
    const float* sB3f = reinterpret_cast<const float*>(sm + SM_B3);

    const int g = lane >> 2, tig = lane & 3;
    const int rt = wid >> 2, ct = wid & 3;
    const int r0 = rt * 32;
    const int row = tid >> 2, q = tid & 3;
    const int barid = 1 + rt;           // named barrier per 4-warp group
    const int qh = lane >> 3;           // quad for x4t addressing
    const int ql = lane & 7;

    // Prefetch first object's coords
    float nx0 = 0.f, nx1 = 0.f, nx2 = 0.f;
    if (blockIdx.x < (unsigned)ntot) {
        const float* pr = pts + (size_t)blockIdx.x * 384 + row * 3;
        nx0 = pr[0]; nx1 = pr[1]; nx2 = pr[2];
    }

    for (int obj = blockIdx.x; obj < ntot; obj += gridDim.x) {
        // ---- H1 = relu(pts@W1 + b1) -> sH1 rows [32rt, 32rt+32) ----
        {
            const float x0 = nx0, x1 = nx1, x2 = nx2;
            uint32_t u[8];
            #pragma unroll
            for (int e = 0; e < 8; e++) {
                const int c0 = q * 16 + e * 2;
                float v0 = fmaf(x2, sW1f[128 + c0],
                           fmaf(x1, sW1f[64 + c0], fmaf(x0, sW1f[c0], sB1f[c0])));
                float v1 = fmaf(x2, sW1f[129 + c0],
                           fmaf(x1, sW1f[65 + c0], fmaf(x0, sW1f[c0 + 1], sB1f[c0 + 1])));
                u[e] = pack2(fmaxf(v0, 0.f), fmaxf(v1, 0.f));
            }
            const int ch0 = (q * 2) ^ (row & 7), ch1 = (q * 2 + 1) ^ (row & 7);
            *reinterpret_cast<uint4*>(sm + SM_H1 + row * 128 + ch0 * 16) =
                make_uint4(u[0], u[1], u[2], u[3]);
            *reinterpret_cast<uint4*>(sm + SM_H1 + row * 128 + ch1 * 16) =
                make_uint4(u[4], u[5], u[6], u[7]);
            // Prefetch next object's coords
            const int nobj = obj + gridDim.x;
            if (nobj < ntot) {
                const float* pr = pts + (size_t)nobj * 384 + row * 3;
                nx0 = pr[0]; nx1 = pr[1]; nx2 = pr[2];
            }
        }
        NAMED_BAR(barid);   // group's H1 rows ready

        // ---- Phase 1: H2 rows = relu(H1 @ W2 + b2), B double-buffered ----
        {
            const int n0 = ct * 32;
            uint32_t a[2][4][4];
            #pragma unroll
            for (int rg = 0; rg < 2; rg++)
                #pragma unroll
                for (int kb = 0; kb < 4; kb++) {
                    const int rr = r0 + rg * 16 + (lane & 15);
                    const int ch = (kb * 2 + (lane >> 4)) ^ (rr & 7);
                    ldsm_x4(a[rg][kb][0], a[rg][kb][1], a[rg][kb][2], a[rg][kb][3],
                            s0 + SM_H1 + rr * 128 + ch * 16);
                }
            float c[2][4][4] = {};
            uint32_t bb[2][8];
            {
                const int krow = (qh & 1) * 8 + ql;
                #pragma unroll
                for (int jp = 0; jp < 2; jp++) {
                    const int nch = (n0 >> 3) + jp * 2 + (qh >> 1);
                    ldsm_x4t(bb[0][jp*4+0], bb[0][jp*4+1], bb[0][jp*4+2], bb[0][jp*4+3],
                             s0 + SM_W2 + krow * 256 + ((nch ^ (krow & 7)) * 16));
                }
            }
            #pragma unroll
            for (int kb = 0; kb < 4; kb++) {
                const int cur = kb & 1, nxt = cur ^ 1;
                if (kb < 3) {
                    const int krow = (kb + 1) * 16 + (qh & 1) * 8 + ql;
                    #pragma unroll
                    for (int jp = 0; jp < 2; jp++) {
                        const int nch = (n0 >> 3) + jp * 2 + (qh >> 1);
                        ldsm_x4t(bb[nxt][jp*4+0], bb[nxt][jp*4+1],
                                 bb[nxt][jp*4+2], bb[nxt][jp*4+3],
                                 s0 + SM_W2 + krow * 256 + ((nch ^ (krow & 7)) * 16));
                    }
                }
                #pragma unroll
                for (int jp = 0; jp < 2; jp++) {
                    mma16816(c[0][jp*2],     a[0][kb], bb[cur][jp*4+0], bb[cur][jp*4+1]);
                    mma16816(c[1][jp*2],     a[1][kb], bb[cur][jp*4+0], bb[cur][jp*4+1]);
                    mma16816(c[0][jp*2+1],   a[0][kb], bb[cur][jp*4+2], bb[cur][jp*4+3]);
                    mma16816(c[1][jp*2+1],   a[1][kb], bb[cur][jp*4+2], bb[cur][jp*4+3]);
                }
            }
            #pragma unroll
            for (int rg = 0; rg < 2; rg++) {
                const int rowa = r0 + rg * 16 + g, rowb = rowa + 8;
                #pragma unroll
                for (int nb = 0; nb < 4; nb++) {
                    const int col = n0 + nb * 8 + 2 * tig;
                    const float bb0 = sB2f[col], bb1 = sB2f[col + 1];
                    const uint32_t p0 = pack2(fmaxf(c[rg][nb][0] + bb0, 0.f),
                                              fmaxf(c[rg][nb][1] + bb1, 0.f));
                    const uint32_t p1 = pack2(fmaxf(c[rg][nb][2] + bb0, 0.f),
                                              fmaxf(c[rg][nb][3] + bb1, 0.f));
                    const int nch = (n0 >> 3) + nb;
                    *reinterpret_cast<uint32_t*>(
                        sm + SM_H2 + rowa * 256 + ((nch ^ (rowa & 7)) * 16) + tig * 4) = p0;
                    *reinterpret_cast<uint32_t*>(
                        sm + SM_H2 + rowb * 256 + ((nch ^ (rowb & 7)) * 16) + tig * 4) = p1;
                }
            }
        }
        NAMED_BAR(barid);   // group's H2 rows ready

        // ---- Phase 2: H3 = H2 @ W3, B double-buffered; partial col-max ----
        {
            uint32_t a[2][8][4];
            #pragma unroll
            for (int rg = 0; rg < 2; rg++)
                #pragma unroll
                for (int kb = 0; kb < 8; kb++) {
                    const int rr = r0 + rg * 16 + (lane & 15);
                    const int ch = (kb * 2 + (lane >> 4)) ^ (rr & 7);
                    ldsm_x4(a[rg][kb][0], a[rg][kb][1], a[rg][kb][2], a[rg][kb][3],
                            s0 + SM_H2 + rr * 256 + ch * 16);
                }
            float* outp = featp + ((size_t)rt * NTOT + obj) * 256;
            #pragma unroll
            for (int tile = 0; tile < 2; tile++) {
                const int n0 = ct * 32 + tile * 128;
                float c[2][4][4] = {};
                uint32_t bb[2][8];
                {
                    const int krow = (qh & 1) * 8 + ql;
                    #pragma unroll
                    for (int jp = 0; jp < 2; jp++) {
                        const int nch = (n0 >> 3) + jp * 2 + (qh >> 1);
                        ldsm_x4t(bb[0][jp*4+0], bb[0][jp*4+1], bb[0][jp*4+2], bb[0][jp*4+3],
                                 s0 + SM_W3 + krow * 512 + ((nch ^ (krow & 7)) * 16));
                    }
                }
                #pragma unroll
                for (int kb = 0; kb < 8; kb++) {
                    const int cur = kb & 1, nxt = cur ^ 1;
                    if (kb < 7) {
                        const int krow = (kb + 1) * 16 + (qh & 1) * 8 + ql;
                        #pragma unroll
                        for (int jp = 0; jp < 2; jp++) {
                            const int nch = (n0 >> 3) + jp * 2 + (qh >> 1);
                            ldsm_x4t(bb[nxt][jp*4+0], bb[nxt][jp*4+1],
                                     bb[nxt][jp*4+2], bb[nxt][jp*4+3],
                                     s0 + SM_W3 + krow * 512 + ((nch ^ (krow & 7)) * 16));
                        }
                    }
                    #pragma unroll
                    for (int jp = 0; jp < 2; jp++) {
                        mma16816(c[0][jp*2],     a[0][kb], bb[cur][jp*4+0], bb[cur][jp*4+1]);
                        mma16816(c[1][jp*2],     a[1][kb], bb[cur][jp*4+0], bb[cur][jp*4+1]);
                        mma16816(c[0][jp*2+1],   a[0][kb], bb[cur][jp*4+2], bb[cur][jp*4+3]);
                        mma16816(c[1][jp*2+1],   a[1][kb], bb[cur][jp*4+2], bb[cur][jp*4+3]);
                    }
                }
                #pragma unroll
                for (int nb = 0; nb < 4; nb++) {
                    float m0 = fmaxf(fmaxf(c[0][nb][0], c[0][nb][2]),
                                     fmaxf(c[1][nb][0], c[1][nb][2]));
                    float m1 = fmaxf(fmaxf(c[0][nb][1], c[0][nb][3]),
                                     fmaxf(c[1][nb][1], c[1][nb][3]));
                    #pragma unroll
                    for (int off = 4; off < 32; off <<= 1) {
                        m0 = fmaxf(m0, __shfl_xor_sync(0xffffffff, m0, off));
                        m1 = fmaxf(m1, __shfl_xor_sync(0xffffffff, m1, off));
                    }
                    if (lane < 4) {
                        const int col = n0 + nb * 8 + 2 * tig;
                        float2 v = make_float2(m0 + sB3f[col], m1 + sB3f[col + 1]);
                        *reinterpret_cast<float2*>(outp + col) = v;
                    }
                }
            }
        }
        // no block-wide sync: groups drift freely; cross-group max happens in heads.
    }
}

// ============================== sgnet mma GEMM (128-row tiles) ==============================
template <bool GATHER, bool RELU, bool IN_F16, bool OUT_F16, int NPAD>
__global__ __launch_bounds__(512) void mma_gemm(
    const void* __restrict__ Ain,
    const float* __restrict__ Asrc, const float* __restrict__ Aref,
    const float* __restrict__ W, const float* __restrict__ bias,
    void* __restrict__ Cout, int nmax, int ldc, int coff)
{
    extern __shared__ char sm[];
    const uint32_t s0 = smem_u32(sm);
    char* sA = sm;                         // 128 x 512B
    char* sW = sm + 65536;                 // 256 x (NPAD*2)B
    float* sBias = reinterpret_cast<float*>(sW + 256 * NPAD * 2);

    const int tid = threadIdx.x;
    const int wid = tid >> 5, lane = tid & 31;
    const int m0 = blockIdx.x * 128;

    {
        const int r = tid >> 2, q = tid & 3;
        const int m = m0 + r;
        if (IN_F16) {
            const __half* arow = reinterpret_cast<const __half*>(Ain) + (size_t)m * 256;
            #pragma unroll
            for (int e = 0; e < 8; e++) {
                const int c = q * 8 + e;
                uint4 u = *reinterpret_cast<const uint4*>(arow + c * 8);
                *reinterpret_cast<uint4*>(sA + r * 512 + ((c ^ (r & 7)) * 16)) = u;
            }
        } else {
            const float* arow;
            if (GATHER) {
                const int b = m >> 10, j = m & 1023;
                arow = (j < 512) ? (Asrc + (size_t)(b * 512 + j) * 256)
                                 : (Aref + (size_t)(b * 512 + (j - 512)) * 256);
            } else {
                arow = reinterpret_cast<const float*>(Ain) + (size_t)m * 256;
            }
            #pragma unroll
            for (int e = 0; e < 8; e++) {
                const int c = q * 8 + e;
                float4 f0 = *reinterpret_cast<const float4*>(arow + c * 8);
                float4 f1 = *reinterpret_cast<const float4*>(arow + c * 8 + 4);
                uint4 u = make_uint4(pack2(f0.x, f0.y), pack2(f0.z, f0.w),
                                     pack2(f1.x, f1.y), pack2(f1.z, f1.w));
                *reinterpret_cast<uint4*>(sA + r * 512 + ((c ^ (r & 7)) * 16)) = u;
            }
        }
    }
    {
        const int r = tid >> 1, h = tid & 1;
        const int CH = NPAD / 16;
        #pragma unroll
        for (int e = 0; e < CH; e++) {
            const int c = h * CH + e;
            float4 f0 = *reinterpret_cast<const float4*>(W + (size_t)r * nmax + c * 8);
            float4 f1 = *reinterpret_cast<const float4*>(W + (size_t)r * nmax + c * 8 + 4);
            uint4 u = make_uint4(pack2(f0.x, f0.y), pack2(f0.z, f0.w),
                                 pack2(f1.x, f1.y), pack2(f1.z, f1.w));
            *reinterpret_cast<uint4*>(sW + r * (NPAD * 2) + ((c ^ (r & 7)) * 16)) = u;
        }
    }
    if (tid < NPAD) sBias[tid] = (tid < nmax) ? bias[tid] : 0.f;
    __syncthreads();

    const int g = lane >> 2, tig = lane & 3;
    const int rt = wid >> 2, ct = wid & 3;
    const int r0 = rt * 32;
    const int NJ = NPAD / 32;
    const int n0 = ct * (NPAD / 4);

    float c[2][NPAD / 32][4];
    #pragma unroll
    for (int rg = 0; rg < 2; rg++)
        #pragma unroll
        for (int j = 0; j < NJ; j++)
            #pragma unroll
            for (int e = 0; e < 4; e++) c[rg][j][e] = 0.f;

    const uint32_t wRowB = NPAD * 2;
    #pragma unroll
    for (int kb = 0; kb < 16; kb++) {
        uint32_t a[2][4];
        #pragma unroll
        for (int rg = 0; rg < 2; rg++) {
            const int rr = r0 + rg * 16 + (lane & 15);
            const int ch = (kb * 2 + (lane >> 4)) ^ (rr & 7);
            ldsm_x4(a[rg][0], a[rg][1], a[rg][2], a[rg][3],
                    s0 + rr * 512 + ch * 16);
        }
        const int krow = kb * 16 + (lane & 15);
        #pragma unroll
        for (int j = 0; j < NJ; j++) {
            const int nch = (n0 >> 3) + j;
            uint32_t b0, b1;
            ldsm_x2t(b0, b1, s0 + 65536 + krow * wRowB + ((nch ^ (krow & 7)) * 16));
            mma16816(c[0][j], a[0], b0, b1);
            mma16816(c[1][j], a[1], b0, b1);
        }
    }

    #pragma unroll
    for (int rg = 0; rg < 2; rg++) {
        const int rowa = m0 + r0 + rg * 16 + g;
        #pragma unroll
        for (int j = 0; j < NJ; j++) {
            const int col = n0 + j * 8 + 2 * tig;
            float v0 = c[rg][j][0] + sBias[col];
            float v1 = c[rg][j][1] + sBias[col + 1];
            float v2 = c[rg][j][2] + sBias[col];
            float v3 = c[rg][j][3] + sBias[col + 1];
            if (RELU) {
                v0 = fmaxf(v0, 0.f); v1 = fmaxf(v1, 0.f);
                v2 = fmaxf(v2, 0.f); v3 = fmaxf(v3, 0.f);
            }
            if (OUT_F16) {
                __half* y = reinterpret_cast<__half*>(Cout);
                *reinterpret_cast<uint32_t*>(y + (size_t)rowa * 256 + col) = pack2(v0, v1);
                *reinterpret_cast<uint32_t*>(y + (size_t)(rowa + 8) * 256 + col) = pack2(v2, v3);
            } else {
                float* o = reinterpret_cast<float*>(Cout);
                if (col < nmax) {
                    o[(size_t)rowa * ldc + coff + col] = v0;
                    o[(size_t)(rowa + 8) * ldc + coff + col] = v2;
                }
                if (col + 1 < nmax) {
                    o[(size_t)rowa * ldc + coff + col + 1] = v1;
                    o[(size_t)(rowa + 8) * ldc + coff + col + 1] = v3;
                }
            }
        }
    }
}

// ============================== fused output heads (se + oe) ==============================
// blocks [0,128): out[:,0:100]  = h2 @ se_w + se_b     (f16 A)
// blocks [128,256): out[:,100:200] = max4(featp) @ oe_w + oe_b
__global__ __launch_bounds__(512) void heads_gemm(
    const __half* __restrict__ h2, const float* __restrict__ featp,
    const float* __restrict__ se_w, const float* __restrict__ se_b,
    const float* __restrict__ oe_w, const float* __restrict__ oe_b,
    float* __restrict__ out)
{
    extern __shared__ char sm[];
    const uint32_t s0 = smem_u32(sm);
    char* sA = sm;                         // 128 x 512B
    char* sW = sm + 65536;                 // 256 x 256B
    float* sBias = reinterpret_cast<float*>(sW + 256 * 256);

    const bool second = blockIdx.x >= 128;
    const int m0 = (blockIdx.x & 127) * 128;
    const float* W = second ? oe_w : se_w;
    const float* bias = second ? oe_b : se_b;
    const int coff = second ? 100 : 0;

    const int tid = threadIdx.x;
    const int wid = tid >> 5, lane = tid & 31;

    {
        const int r = tid >> 2, q = tid & 3;
        const int m = m0 + r;
        if (!second) {
            const __half* arow = h2 + (size_t)m * 256;
            #pragma unroll
            for (int e = 0; e < 8; e++) {
                const int c = q * 8 + e;
                uint4 u = *reinterpret_cast<const uint4*>(arow + c * 8);
                *reinterpret_cast<uint4*>(sA + r * 512 + ((c ^ (r & 7)) * 16)) = u;
            }
        } else {
            const float* arow = featp + (size_t)m * 256;
            #pragma unroll
            for (int e = 0; e < 8; e++) {
                const int c = q * 8 + e;
                float4 f0 = *reinterpret_cast<const float4*>(arow + c * 8);
                float4 f1 = *reinterpret_cast<const float4*>(arow + c * 8 + 4);
                #pragma unroll
                for (int p = 1; p < 4; p++) {
                    const float* ar = arow + (size_t)p * NTOT * 256;
                    float4 g0 = *reinterpret_cast<const float4*>(ar + c * 8);
                    float4 g1 = *reinterpret_cast<const float4*>(ar + c * 8 + 4);
                    f0.x = fmaxf(f0.x, g0.x); f0.y = fmaxf(f0.y, g0.y);
                    f0.z = fmaxf(f0.z, g0.z); f0.w = fmaxf(f0.w, g0.w);
                    f1.x = fmaxf(f1.x, g1.x); f1.y = fmaxf(f1.y, g1.y);
                    f1.z = fmaxf(f1.z, g1.z); f1.w = fmaxf(f1.w, g1.w);
                }
                uint4 u = make_uint4(pack2(f0.x, f0.y), pack2(f0.z, f0.w),
                                     pack2(f1.x, f1.y), pack2(f1.z, f1.w));
                *reinterpret_cast<uint4*>(sA + r * 512 + ((c ^ (r & 7)) * 16)) = u;
            }
        }
    }
    {
        const int r = tid >> 1, h = tid & 1;
        #pragma unroll
        for (int e = 0; e < 8; e++) {
            const int c = h * 8 + e;
            float v[8];
            #pragma unroll
            for (int i = 0; i < 8; i++) {
                const int col = c * 8 + i;
                v[i] = (col < EMB) ? W[(size_t)r * EMB + col] : 0.f;
            }
            uint4 u = make_uint4(pack2(v[0], v[1]), pack2(v[2], v[3]),
                                 pack2(v[4], v[5]), pack2(v[6], v[7]));
            *reinterpret_cast<uint4*>(sW + r * 256 + ((c ^ (r & 7)) * 16)) = u;
        }
    }
    if (tid < 128) sBias[tid] = (tid < EMB) ? bias[tid] : 0.f;
    __syncthreads();

    const int g = lane >> 2, tig = lane & 3;
    const int rt = wid >> 2, ct = wid & 3;
    const int r0 = rt * 32;
    const int n0 = ct * 32;

    float c[2][4][4] = {};
    #pragma unroll
    for (int kb = 0; kb < 16; kb++) {
        uint32_t a[2][4];
        #pragma unroll
        for (int rg = 0; rg < 2; rg++) {
            const int rr = r0 + rg * 16 + (lane & 15);
            const int ch = (kb * 2 + (lane >> 4)) ^ (rr & 7);
            ldsm_x4(a[rg][0], a[rg][1], a[rg][2], a[rg][3],
                    s0 + rr * 512 + ch * 16);
        }
        const int krow = kb * 16 + (lane & 15);
        #pragma unroll
        for (int j = 0; j < 4; j++) {
            const int nch = (n0 >> 3) + j;
            uint32_t b0, b1;
            ldsm_x2t(b0, b1, s0 + 65536 + krow * 256 + ((nch ^ (krow & 7)) * 16));
            mma16816(c[0][j], a[0], b0, b1);
            mma16816(c[1][j], a[1], b0, b1);
        }
    }

    #pragma unroll
    for (int rg = 0; rg < 2; rg++) {
        const int rowa = m0 + r0 + rg * 16 + g;
        #pragma unroll
        for (int j = 0; j < 4; j++) {
            const int col = n0 + j * 8 + 2 * tig;
            float v0 = c[rg][j][0] + sBias[col];
            float v1 = c[rg][j][1] + sBias[col + 1];
            float v2 = c[rg][j][2] + sBias[col];
            float v3 = c[rg][j][3] + sBias[col + 1];
            if (col < EMB) {
                out[(size_t)rowa * 200 + coff + col] = v0;
                out[(size_t)(rowa + 8) * 200 + coff + col] = v2;
            }
            if (col + 1 < EMB) {
                out[(size_t)rowa * 200 + coff + col + 1] = v1;
                out[(size_t)(rowa + 8) * 200 + coff + col + 1] = v3;
            }
        }
    }
}

// ============================== Launch ==============================
extern "C" void kernel_launch(void* const* d_in, const int* in_sizes, int n_in,
                              void* d_out, int out_size)
{
    const float* tot_obj_pts = (const float*)d_in[0];
    const float* src_feat    = (const float*)d_in[1];
    const float* ref_feat    = (const float*)d_in[2];
    const float* sg_w1 = (const float*)d_in[6];
    const float* sg_b1 = (const float*)d_in[7];
    const float* sg_w2 = (const float*)d_in[8];
    const float* sg_b2 = (const float*)d_in[9];
    const float* se_w  = (const float*)d_in[10];
    const float* se_b  = (const float*)d_in[11];
    const float* p_w1  = (const float*)d_in[12];
    const float* p_b1  = (const float*)d_in[13];
    const float* p_w2  = (const float*)d_in[14];
    const float* p_b2  = (const float*)d_in[15];
    const float* p_w3  = (const float*)d_in[16];
    const float* p_b3  = (const float*)d_in[17];
    const float* oe_w  = (const float*)d_in[18];
    const float* oe_b  = (const float*)d_in[19];
    float* out = (float*)d_out;

    void *ph1, *ph2, *pfeat;
    cudaGetSymbolAddress(&ph1, g_h1);
    cudaGetSymbolAddress(&ph2, g_h2);
    cudaGetSymbolAddress(&pfeat, g_feat);

    int sms = 148;
    cudaDeviceGetAttribute(&sms, cudaDevAttrMultiProcessorCount, 0);

    cudaFuncSetAttribute(pointnet_mma,
                         cudaFuncAttributeMaxDynamicSharedMemorySize, SM_TOTAL);

    // PointNet branch (dominant) — writes 4 per-group partial max buffers
    pointnet_mma<<<sms, 512, SM_TOTAL>>>(
        tot_obj_pts, p_w1, p_b1, p_w2, p_b2, p_w3, p_b3, (float*)pfeat, NTOT);

    // sgnet chain on tensor cores
    const int SMEM_256 = 65536 + 131072 + 1024;   // 197632
    const int SMEM_128 = 65536 + 65536 + 512;     // 131584

    auto k1 = mma_gemm<true,  true,  false, true,  256>;
    auto k2 = mma_gemm<false, false, true,  true,  256>;
    cudaFuncSetAttribute(k1, cudaFuncAttributeMaxDynamicSharedMemorySize, SMEM_256);
    cudaFuncSetAttribute(k2, cudaFuncAttributeMaxDynamicSharedMemorySize, SMEM_256);
    cudaFuncSetAttribute(heads_gemm, cudaFuncAttributeMaxDynamicSharedMemorySize, SMEM_128);

    // h1 = relu(gather(src,ref) @ sg_w1 + sg_b1)
    k1<<<NTOT / 128, 512, SMEM_256>>>(nullptr, src_feat, ref_feat,
                                      sg_w1, sg_b1, ph1, 256, 0, 0);
    // h2 = h1 @ sg_w2 + sg_b2
    k2<<<NTOT / 128, 512, SMEM_256>>>(ph1, nullptr, nullptr,
                                      sg_w2, sg_b2, ph2, 256, 0, 0);
    // fused: out[:,0:100] = h2@se_w+se_b ; out[:,100:200] = max4(featp)@oe_w+oe_b
    heads_gemm<<<2 * (NTOT / 128), 512, SMEM_128>>>(
        (const __half*)ph2, (const float*)pfeat, se_w, se_b, oe_w, oe_b, out);
}

// round 11
// speedup vs baseline: 1.0432x; 1.0432x over previous
#include <cuda_runtime.h>
#include <cuda_fp16.h>
#include <cstdint>

#define NTOT 16384
#define EMB  100

// Scratch (device globals — no runtime allocation allowed).
__device__ __half g_feat[4 * NTOT * 256]; // per-group partial col-max (+b3), f16

// ============================== helpers ==============================
__device__ __forceinline__ uint32_t smem_u32(const void* p) {
    uint32_t a;
    asm("{ .reg .u64 t; cvta.to.shared.u64 t, %1; cvt.u32.u64 %0, t; }"
        : "=r"(a) : "l"(p));
    return a;
}
__device__ __forceinline__ uint32_t pack2(float lo, float hi) {
    __half2 h = __floats2half2_rn(lo, hi);
    return *reinterpret_cast<uint32_t*>(&h);
}
__device__ __forceinline__ void ldsm_x4(uint32_t& r0, uint32_t& r1, uint32_t& r2, uint32_t& r3,
                                        uint32_t addr) {
    asm volatile("ldmatrix.sync.aligned.m8n8.x4.shared.b16 {%0,%1,%2,%3}, [%4];"
                 : "=r"(r0), "=r"(r1), "=r"(r2), "=r"(r3) : "r"(addr));
}
__device__ __forceinline__ void ldsm_x2t(uint32_t& r0, uint32_t& r1, uint32_t addr) {
    asm volatile("ldmatrix.sync.aligned.m8n8.x2.trans.shared.b16 {%0,%1}, [%2];"
                 : "=r"(r0), "=r"(r1) : "r"(addr));
}
__device__ __forceinline__ void ldsm_x4t(uint32_t& r0, uint32_t& r1, uint32_t& r2, uint32_t& r3,
                                         uint32_t addr) {
    asm volatile("ldmatrix.sync.aligned.m8n8.x4.trans.shared.b16 {%0,%1,%2,%3}, [%4];"
                 : "=r"(r0), "=r"(r1), "=r"(r2), "=r"(r3) : "r"(addr));
}
__device__ __forceinline__ void mma16816(float* c, const uint32_t* a, uint32_t b0, uint32_t b1) {
    asm volatile("mma.sync.aligned.m16n8k16.row.col.f32.f16.f16.f32 "
                 "{%0,%1,%2,%3}, {%4,%5,%6,%7}, {%8,%9}, {%0,%1,%2,%3};"
                 : "+f"(c[0]), "+f"(c[1]), "+f"(c[2]), "+f"(c[3])
                 : "r"(a[0]), "r"(a[1]), "r"(a[2]), "r"(a[3]), "r"(b0), "r"(b1));
}
#define NAMED_BAR(id) \
    asm volatile("bar.sync %0, 128;" :: "r"(id) : "memory")

// ============================== PointNet (mma.sync f16) ==============================
// SMEM byte offsets
#define SM_W3   0        /* 128 x 512B  (f16, swizzled)  = 65536 */
#define SM_W2   65536    /* 64  x 256B                    = 16384 */
#define SM_H2   81920    /* 128 x 256B                    = 32768 */
#define SM_H1   114688   /* 128 x 128B                    = 16384 */
#define SM_B2   131072   /* 128 f32 */
#define SM_B3   131584   /* 256 f32 */
#define SM_W1   132608   /* 192 f32 */
#define SM_B1   133376   /* 64  f32 */
#define SM_TOTAL 133632

__global__ __launch_bounds__(512, 1) void pointnet_mma(
    const float* __restrict__ pts,
    const float* __restrict__ w1, const float* __restrict__ b1,
    const float* __restrict__ w2, const float* __restrict__ b2,
    const float* __restrict__ w3, const float* __restrict__ b3,
    __half* __restrict__ featp, int ntot)
{
    extern __shared__ char sm[];
    const uint32_t s0 = smem_u32(sm);
    const int tid = threadIdx.x;
    const int wid = tid >> 5, lane = tid & 31;

    // ---- Stage weights (once per block) ----
    for (int i = tid * 8; i < 128 * 256; i += 512 * 8) {
        int k = i >> 8, n = i & 255;
        float4 f0 = *reinterpret_cast<const float4*>(w3 + i);
        float4 f1 = *reinterpret_cast<const float4*>(w3 + i + 4);
        uint4 u = make_uint4(pack2(f0.x, f0.y), pack2(f0.z, f0.w),
                             pack2(f1.x, f1.y), pack2(f1.z, f1.w));
        int ch = (n >> 3) ^ (k & 7);
        *reinterpret_cast<uint4*>(sm + SM_W3 + k * 512 + ch * 16) = u;
    }
    for (int i = tid * 8; i < 64 * 128; i += 512 * 8) {
        int k = i >> 7, n = i & 127;
        float4 f0 = *reinterpret_cast<const float4*>(w2 + i);
        float4 f1 = *reinterpret_cast<const float4*>(w2 + i + 4);
        uint4 u = make_uint4(pack2(f0.x, f0.y), pack2(f0.z, f0.w),
                             pack2(f1.x, f1.y), pack2(f1.z, f1.w));
        int ch = (n >> 3) ^ (k & 7);
        *reinterpret_cast<uint4*>(sm + SM_W2 + k * 256 + ch * 16) = u;
    }
    if (tid < 128) reinterpret_cast<float*>(sm + SM_B2)[tid] = b2[tid];
    if (tid < 256) reinterpret_cast<float*>(sm + SM_B3)[tid] = b3[tid];
    if (tid < 192) reinterpret_cast<float*>(sm + SM_W1)[tid] = w1[tid];
    if (tid < 64)  reinterpret_cast<float*>(sm + SM_B1)[tid] = b1[tid];
    __syncthreads();   // only block-wide sync in the whole kernel

    const float* sW1f = reinterpret_cast<const float*>(sm + SM_W1);
    const float* sB1f = reinterpret_cast<const float*>(sm + SM_B1);
    const float* sB2f = reinterpret_cast<const float*>(sm + SM_B2);
    const float* sB3f = reinterpret_cast<const float*>(sm + SM_B3);

    const int g = lane >> 2, tig = lane & 3;
    const int rt = wid >> 2, ct = wid & 3;
    const int r0 = rt * 32;
    const int row = tid >> 2, q = tid & 3;
    const int barid = 1 + rt;           // named barrier per 4-warp group
    const int qh = lane >> 3;
    const int ql = lane & 7;

    // Prefetch first object's coords
    float nx0 = 0.f, nx1 = 0.f, nx2 = 0.f;
    if (blockIdx.x < (unsigned)ntot) {
        const float* pr = pts + (size_t)blockIdx.x * 384 + row * 3;
        nx0 = pr[0]; nx1 = pr[1]; nx2 = pr[2];
    }

    for (int obj = blockIdx.x; obj < ntot; obj += gridDim.x) {
        // ---- H1 = relu(pts@W1 + b1) -> sH1 rows [32rt, 32rt+32) ----
        {
            const float x0 = nx0, x1 = nx1, x2 = nx2;
            uint32_t u[8];
            #pragma unroll
            for (int e = 0; e < 8; e++) {
                const int c0 = q * 16 + e * 2;
                float v0 = fmaf(x2, sW1f[128 + c0],
                           fmaf(x1, sW1f[64 + c0], fmaf(x0, sW1f[c0], sB1f[c0])));
                float v1 = fmaf(x2, sW1f[129 + c0],
                           fmaf(x1, sW1f[65 + c0], fmaf(x0, sW1f[c0 + 1], sB1f[c0 + 1])));
                u[e] = pack2(fmaxf(v0, 0.f), fmaxf(v1, 0.f));
            }
            const int ch0 = (q * 2) ^ (row & 7), ch1 = (q * 2 + 1) ^ (row & 7);
            *reinterpret_cast<uint4*>(sm + SM_H1 + row * 128 + ch0 * 16) =
                make_uint4(u[0], u[1], u[2], u[3]);
            *reinterpret_cast<uint4*>(sm + SM_H1 + row * 128 + ch1 * 16) =
                make_uint4(u[4], u[5], u[6], u[7]);
            const int nobj = obj + gridDim.x;
            if (nobj < ntot) {
                const float* pr = pts + (size_t)nobj * 384 + row * 3;
                nx0 = pr[0]; nx1 = pr[1]; nx2 = pr[2];
            }
        }
        NAMED_BAR(barid);

        // ---- Phase 1: H2 rows = relu(H1 @ W2 + b2), warp tile 32x32 ----
        {
            const int n0 = ct * 32;
            uint32_t a[2][4][4];
            #pragma unroll
            for (int rg = 0; rg < 2; rg++)
                #pragma unroll
                for (int kb = 0; kb < 4; kb++) {
                    const int rr = r0 + rg * 16 + (lane & 15);
                    const int ch = (kb * 2 + (lane >> 4)) ^ (rr & 7);
                    ldsm_x4(a[rg][kb][0], a[rg][kb][1], a[rg][kb][2], a[rg][kb][3],
                            s0 + SM_H1 + rr * 128 + ch * 16);
                }
            float c[2][4][4] = {};
            #pragma unroll
            for (int kb = 0; kb < 4; kb++) {
                const int krow = kb * 16 + (qh & 1) * 8 + ql;
                #pragma unroll
                for (int jp = 0; jp < 2; jp++) {
                    const int nch = (n0 >> 3) + jp * 2 + (qh >> 1);
                    uint32_t b0, b1, b2r, b3r;
                    ldsm_x4t(b0, b1, b2r, b3r,
                             s0 + SM_W2 + krow * 256 + ((nch ^ (krow & 7)) * 16));
                    mma16816(c[0][jp * 2],     a[0][kb], b0, b1);
                    mma16816(c[1][jp * 2],     a[1][kb], b0, b1);
                    mma16816(c[0][jp * 2 + 1], a[0][kb], b2r, b3r);
                    mma16816(c[1][jp * 2 + 1], a[1][kb], b2r, b3r);
                }
            }
            #pragma unroll
            for (int rg = 0; rg < 2; rg++) {
                const int rowa = r0 + rg * 16 + g, rowb = rowa + 8;
                #pragma unroll
                for (int nb = 0; nb < 4; nb++) {
                    const int col = n0 + nb * 8 + 2 * tig;
                    const float bb0 = sB2f[col], bb1 = sB2f[col + 1];
                    const uint32_t p0 = pack2(fmaxf(c[rg][nb][0] + bb0, 0.f),
                                              fmaxf(c[rg][nb][1] + bb1, 0.f));
                    const uint32_t p1 = pack2(fmaxf(c[rg][nb][2] + bb0, 0.f),
                                              fmaxf(c[rg][nb][3] + bb1, 0.f));
                    const int nch = (n0 >> 3) + nb;
                    *reinterpret_cast<uint32_t*>(
                        sm + SM_H2 + rowa * 256 + ((nch ^ (rowa & 7)) * 16) + tig * 4) = p0;
                    *reinterpret_cast<uint32_t*>(
                        sm + SM_H2 + rowb * 256 + ((nch ^ (rowb & 7)) * 16) + tig * 4) = p1;
                }
            }
        }
        NAMED_BAR(barid);

        // ---- Phase 2: H3 = H2 @ W3; partial col-max over the group's 32 rows ----
        {
            uint32_t a[2][8][4];
            #pragma unroll
            for (int rg = 0; rg < 2; rg++)
                #pragma unroll
                for (int kb = 0; kb < 8; kb++) {
                    const int rr = r0 + rg * 16 + (lane & 15);
                    const int ch = (kb * 2 + (lane >> 4)) ^ (rr & 7);
                    ldsm_x4(a[rg][kb][0], a[rg][kb][1], a[rg][kb][2], a[rg][kb][3],
                            s0 + SM_H2 + rr * 256 + ch * 16);
                }
            __half* outp = featp + ((size_t)rt * NTOT + obj) * 256;
            #pragma unroll
            for (int tile = 0; tile < 2; tile++) {
                const int n0 = ct * 32 + tile * 128;
                float c[2][4][4] = {};
                #pragma unroll
                for (int kb = 0; kb < 8; kb++) {
                    const int krow = kb * 16 + (qh & 1) * 8 + ql;
                    #pragma unroll
                    for (int jp = 0; jp < 2; jp++) {
                        const int nch = (n0 >> 3) + jp * 2 + (qh >> 1);
                        uint32_t b0, b1, b2r, b3r;
                        ldsm_x4t(b0, b1, b2r, b3r,
                                 s0 + SM_W3 + krow * 512 + ((nch ^ (krow & 7)) * 16));
                        mma16816(c[0][jp * 2],     a[0][kb], b0, b1);
                        mma16816(c[1][jp * 2],     a[1][kb], b0, b1);
                        mma16816(c[0][jp * 2 + 1], a[0][kb], b2r, b3r);
                        mma16816(c[1][jp * 2 + 1], a[1][kb], b2r, b3r);
                    }
                }
                #pragma unroll
                for (int nb = 0; nb < 4; nb++) {
                    float m0 = fmaxf(fmaxf(c[0][nb][0], c[0][nb][2]),
                                     fmaxf(c[1][nb][0], c[1][nb][2]));
                    float m1 = fmaxf(fmaxf(c[0][nb][1], c[0][nb][3]),
                                     fmaxf(c[1][nb][1], c[1][nb][3]));
                    #pragma unroll
                    for (int off = 4; off < 32; off <<= 1) {
                        m0 = fmaxf(m0, __shfl_xor_sync(0xffffffff, m0, off));
                        m1 = fmaxf(m1, __shfl_xor_sync(0xffffffff, m1, off));
                    }
                    if (lane < 4) {
                        const int col = n0 + nb * 8 + 2 * tig;
                        __half2 hv = __floats2half2_rn(m0 + sB3f[col], m1 + sB3f[col + 1]);
                        *reinterpret_cast<__half2*>(outp + col) = hv;
                    }
                }
            }
        }
        // no block-wide sync: groups drift freely; cross-group max happens in oe_head.
    }
}

// ============================== shared GEMM building blocks ==============================
// A tile: 128 rows x 512B f16 swizzled. W tile: 256 rows x 512B.
__device__ __forceinline__ void gemm_loop_256(
    float (&c)[2][8][4], uint32_t sA0, uint32_t sW0, int r0, int n0, int lane)
{
    #pragma unroll
    for (int kb = 0; kb < 16; kb++) {
        uint32_t a[2][4];
        #pragma unroll
        for (int rg = 0; rg < 2; rg++) {
            const int rr = r0 + rg * 16 + (lane & 15);
            const int ch = (kb * 2 + (lane >> 4)) ^ (rr & 7);
            ldsm_x4(a[rg][0], a[rg][1], a[rg][2], a[rg][3], sA0 + rr * 512 + ch * 16);
        }
        const int krow = kb * 16 + (lane & 15);
        #pragma unroll
        for (int j = 0; j < 8; j++) {
            const int nch = (n0 >> 3) + j;
            uint32_t b0, b1;
            ldsm_x2t(b0, b1, sW0 + krow * 512 + ((nch ^ (krow & 7)) * 16));
            mma16816(c[0][j], a[0], b0, b1);
            mma16816(c[1][j], a[1], b0, b1);
        }
    }
}

// write (relu?)(C + bias) as f16 into sA (swizzled, rowBytes 512)
__device__ __forceinline__ void write_h_f16(
    char* sA, float (&c)[2][8][4], const float* sBias,
    int r0, int n0, int g, int tig, bool relu)
{
    #pragma unroll
    for (int rg = 0; rg < 2; rg++) {
        const int rowa = r0 + rg * 16 + g, rowb = rowa + 8;
        #pragma unroll
        for (int j = 0; j < 8; j++) {
            const int col = n0 + j * 8 + 2 * tig;
            const float bb0 = sBias[col], bb1 = sBias[col + 1];
            float v0 = c[rg][j][0] + bb0, v1 = c[rg][j][1] + bb1;
            float v2 = c[rg][j][2] + bb0, v3 = c[rg][j][3] + bb1;
            if (relu) {
                v0 = fmaxf(v0, 0.f); v1 = fmaxf(v1, 0.f);
                v2 = fmaxf(v2, 0.f); v3 = fmaxf(v3, 0.f);
            }
            const int nch = (n0 >> 3) + j;
            *reinterpret_cast<uint32_t*>(
                sA + rowa * 512 + ((nch ^ (rowa & 7)) * 16) + tig * 4) = pack2(v0, v1);
            *reinterpret_cast<uint32_t*>(
                sA + rowb * 512 + ((nch ^ (rowb & 7)) * 16) + tig * 4) = pack2(v2, v3);
        }
    }
}

__device__ __forceinline__ void stage_w256(char* sW, const float* __restrict__ W, int tid) {
    const int r = tid >> 1, h = tid & 1;
    #pragma unroll
    for (int e = 0; e < 16; e++) {
        const int c = h * 16 + e;
        float4 f0 = *reinterpret_cast<const float4*>(W + (size_t)r * 256 + c * 8);
        float4 f1 = *reinterpret_cast<const float4*>(W + (size_t)r * 256 + c * 8 + 4);
        uint4 u = make_uint4(pack2(f0.x, f0.y), pack2(f0.z, f0.w),
                             pack2(f1.x, f1.y), pack2(f1.z, f1.w));
        *reinterpret_cast<uint4*>(sW + r * 512 + ((c ^ (r & 7)) * 16)) = u;
    }
}

// stage a 256 x EMB head weight into sW (rowBytes 256, zero-padded to 128 cols)
__device__ __forceinline__ void stage_w_head(char* sW, const float* __restrict__ W, int tid) {
    const int r = tid >> 1, h = tid & 1;
    #pragma unroll
    for (int e = 0; e < 8; e++) {
        const int c = h * 8 + e;
        float v[8];
        #pragma unroll
        for (int i = 0; i < 8; i++) {
            const int col = c * 8 + i;
            v[i] = (col < EMB) ? W[(size_t)r * EMB + col] : 0.f;
        }
        uint4 u = make_uint4(pack2(v[0], v[1]), pack2(v[2], v[3]),
                             pack2(v[4], v[5]), pack2(v[6], v[7]));
        *reinterpret_cast<uint4*>(sW + r * 256 + ((c ^ (r & 7)) * 16)) = u;
    }
}

// head GEMM compute + write out (NPAD=128, wRowB=256)
__device__ __forceinline__ void head_compute(
    uint32_t sA0, uint32_t sW0, const float* sBias, float* __restrict__ out,
    int m0, int coff, int lane, int wid)
{
    const int g = lane >> 2, tig = lane & 3;
    const int rt = wid >> 2, ct = wid & 3;
    const int r0 = rt * 32;
    const int n0 = ct * 32;
    float c[2][4][4] = {};
    #pragma unroll
    for (int kb = 0; kb < 16; kb++) {
        uint32_t a[2][4];
        #pragma unroll
        for (int rg = 0; rg < 2; rg++) {
            const int rr = r0 + rg * 16 + (lane & 15);
            const int ch = (kb * 2 + (lane >> 4)) ^ (rr & 7);
            ldsm_x4(a[rg][0], a[rg][1], a[rg][2], a[rg][3], sA0 + rr * 512 + ch * 16);
        }
        const int krow = kb * 16 + (lane & 15);
        #pragma unroll
        for (int j = 0; j < 4; j++) {
            const int nch = (n0 >> 3) + j;
            uint32_t b0, b1;
            ldsm_x2t(b0, b1, sW0 + krow * 256 + ((nch ^ (krow & 7)) * 16));
            mma16816(c[0][j], a[0], b0, b1);
            mma16816(c[1][j], a[1], b0, b1);
        }
    }
    #pragma unroll
    for (int rg = 0; rg < 2; rg++) {
        const int rowa = m0 + r0 + rg * 16 + g;
        #pragma unroll
        for (int j = 0; j < 4; j++) {
            const int col = n0 + j * 8 + 2 * tig;
            const float v0 = c[rg][j][0] + sBias[col];
            const float v1 = c[rg][j][1] + sBias[col + 1];
            const float v2 = c[rg][j][2] + sBias[col];
            const float v3 = c[rg][j][3] + sBias[col + 1];
            if (col < EMB) {
                out[(size_t)rowa * 200 + coff + col] = v0;
                out[(size_t)(rowa + 8) * 200 + coff + col] = v2;
            }
            if (col + 1 < EMB) {
                out[(size_t)rowa * 200 + coff + col + 1] = v1;
                out[(size_t)(rowa + 8) * 200 + coff + col + 1] = v3;
            }
        }
    }
}

// ============================== fused sgnet: gather -> h1 -> h2 -> se head ==============================
__global__ __launch_bounds__(512) void sg_fused(
    const float* __restrict__ Asrc, const float* __restrict__ Aref,
    const float* __restrict__ w1, const float* __restrict__ b1,
    const float* __restrict__ w2, const float* __restrict__ b2,
    const float* __restrict__ sew, const float* __restrict__ seb,
    float* __restrict__ out)
{
    extern __shared__ char sm[];
    const uint32_t s0 = smem_u32(sm);
    char* sA = sm;                              // 128 x 512B
    char* sW = sm + 65536;                      // 256 x 512B
    float* sBias = reinterpret_cast<float*>(sm + 65536 + 131072);

    const int tid = threadIdx.x;
    const int wid = tid >> 5, lane = tid & 31;
    const int m0 = blockIdx.x * 128;
    const int g = lane >> 2, tig = lane & 3;
    const int rt = wid >> 2, ct = wid & 3;
    const int r0 = rt * 32;
    const int n064 = ct * 64;

    // Stage gathered A + W1 + b1
    {
        const int r = tid >> 2, q = tid & 3;
        const int m = m0 + r;
        const int b = m >> 10, j = m & 1023;
        const float* arow = (j < 512) ? (Asrc + (size_t)(b * 512 + j) * 256)
                                      : (Aref + (size_t)(b * 512 + (j - 512)) * 256);
        #pragma unroll
        for (int e = 0; e < 8; e++) {
            const int c = q * 8 + e;
            float4 f0 = *reinterpret_cast<const float4*>(arow + c * 8);
            float4 f1 = *reinterpret_cast<const float4*>(arow + c * 8 + 4);
            uint4 u = make_uint4(pack2(f0.x, f0.y), pack2(f0.z, f0.w),
                                 pack2(f1.x, f1.y), pack2(f1.z, f1.w));
            *reinterpret_cast<uint4*>(sA + r * 512 + ((c ^ (r & 7)) * 16)) = u;
        }
    }
    stage_w256(sW, w1, tid);
    if (tid < 256) sBias[tid] = b1[tid];
    __syncthreads();

    // C1 = A @ W1
    {
        float c1[2][8][4] = {};
        gemm_loop_256(c1, s0, s0 + 65536, r0, n064, lane);
        __syncthreads();                         // all reads of sA/sW done
        write_h_f16(sA, c1, sBias, r0, n064, g, tig, true);   // h1 = relu(C1+b1)
    }
    __syncthreads();                             // h1 complete; bias reads done
    stage_w256(sW, w2, tid);
    if (tid < 256) sBias[tid] = b2[tid];
    __syncthreads();

    // C2 = h1 @ W2
    {
        float c2[2][8][4] = {};
        gemm_loop_256(c2, s0, s0 + 65536, r0, n064, lane);
        __syncthreads();
        write_h_f16(sA, c2, sBias, r0, n064, g, tig, false);  // h2 = C2+b2
    }
    __syncthreads();
    stage_w_head(sW, sew, tid);
    if (tid < 128) sBias[tid] = (tid < EMB) ? seb[tid] : 0.f;
    __syncthreads();

    // out[:, 0:100] = h2 @ se_w + se_b
    head_compute(s0, s0 + 65536, sBias, out, m0, 0, lane, wid);
}

// ============================== oe head: max4(featp f16) @ oe_w + oe_b ==============================
__global__ __launch_bounds__(512) void oe_head(
    const __half* __restrict__ featp,
    const float* __restrict__ W, const float* __restrict__ bias,
    float* __restrict__ out)
{
    extern __shared__ char sm[];
    const uint32_t s0 = smem_u32(sm);
    char* sA = sm;                              // 128 x 512B
    char* sW = sm + 65536;                      // 256 x 256B
    float* sBias = reinterpret_cast<float*>(sm + 65536 + 65536);

    const int tid = threadIdx.x;
    const int wid = tid >> 5, lane = tid & 31;
    const int m0 = blockIdx.x * 128;

    // Stage A = elementwise max over the 4 partial buffers (f16)
    {
        const int r = tid >> 2, q = tid & 3;
        const int m = m0 + r;
        const __half* arow = featp + (size_t)m * 256;
        #pragma unroll
        for (int e = 0; e < 8; e++) {
            const int c = q * 8 + e;
            uint4 u = *reinterpret_cast<const uint4*>(arow + c * 8);
            __half2* uh = reinterpret_cast<__half2*>(&u);
            #pragma unroll
            for (int p = 1; p < 4; p++) {
                uint4 v = *reinterpret_cast<const uint4*>(
                    arow + (size_t)p * NTOT * 256 + c * 8);
                const __half2* vh = reinterpret_cast<const __half2*>(&v);
                uh[0] = __hmax2(uh[0], vh[0]);
                uh[1] = __hmax2(uh[1], vh[1]);
                uh[2] = __hmax2(uh[2], vh[2]);
                uh[3] = __hmax2(uh[3], vh[3]);
            }
            *reinterpret_cast<uint4*>(sA + r * 512 + ((c ^ (r & 7)) * 16)) = u;
        }
    }
    stage_w_head(sW, W, tid);
    if (tid < 128) sBias[tid] = (tid < EMB) ? bias[tid] : 0.f;
    __syncthreads();

    // out[:, 100:200] = A @ oe_w + oe_b
    head_compute(s0, s0 + 65536, sBias, out, m0, 100, lane, wid);
}

// ============================== Launch ==============================
extern "C" void kernel_launch(void* const* d_in, const int* in_sizes, int n_in,
                              void* d_out, int out_size)
{
    const float* tot_obj_pts = (const float*)d_in[0];
    const float* src_feat    = (const float*)d_in[1];
    const float* ref_feat    = (const float*)d_in[2];
    const float* sg_w1 = (const float*)d_in[6];
    const float* sg_b1 = (const float*)d_in[7];
    const float* sg_w2 = (const float*)d_in[8];
    const float* sg_b2 = (const float*)d_in[9];
    const float* se_w  = (const float*)d_in[10];
    const float* se_b  = (const float*)d_in[11];
    const float* p_w1  = (const float*)d_in[12];
    const float* p_b1  = (const float*)d_in[13];
    const float* p_w2  = (const float*)d_in[14];
    const float* p_b2  = (const float*)d_in[15];
    const float* p_w3  = (const float*)d_in[16];
    const float* p_b3  = (const float*)d_in[17];
    const float* oe_w  = (const float*)d_in[18];
    const float* oe_b  = (const float*)d_in[19];
    float* out = (float*)d_out;

    void* pfeat;
    cudaGetSymbolAddress(&pfeat, g_feat);

    int sms = 148;
    cudaDeviceGetAttribute(&sms, cudaDevAttrMultiProcessorCount, 0);

    const int SG_SMEM = 65536 + 131072 + 1024;   // 197632
    const int OE_SMEM = 65536 + 65536 + 512;     // 131584

    cudaFuncSetAttribute(pointnet_mma,
                         cudaFuncAttributeMaxDynamicSharedMemorySize, SM_TOTAL);
    cudaFuncSetAttribute(sg_fused,
                         cudaFuncAttributeMaxDynamicSharedMemorySize, SG_SMEM);
    cudaFuncSetAttribute(oe_head,
                         cudaFuncAttributeMaxDynamicSharedMemorySize, OE_SMEM);

    // PointNet (dominant, at HMMA roofline) — writes 4 f16 partial-max buffers
    pointnet_mma<<<sms, 512, SM_TOTAL>>>(
        tot_obj_pts, p_w1, p_b1, p_w2, p_b2, p_w3, p_b3, (__half*)pfeat, NTOT);

    // Fused sgnet chain: gather -> h1 -> h2 -> out[:,0:100]
    sg_fused<<<NTOT / 128, 512, SG_SMEM>>>(
        src_feat, ref_feat, sg_w1, sg_b1, sg_w2, sg_b2, se_w, se_b, out);

    // oe head: out[:,100:200] = max4(featp) @ oe_w + oe_b
    oe_head<<<NTOT / 128, 512, OE_SMEM>>>(
        (const __half*)pfeat, oe_w, oe_b, out);
}

// round 12
// speedup vs baseline: 1.0435x; 1.0003x over previous
#include <cuda_runtime.h>
#include <cuda_fp16.h>
#include <cstdint>

#define NTOT 16384
#define EMB  100

// Scratch (device globals — no runtime allocation allowed).
__device__ __half g_feat[4 * NTOT * 256]; // per-group partial col-max (+b3), f16

// ============================== helpers ==============================
__device__ __forceinline__ uint32_t smem_u32(const void* p) {
    uint32_t a;
    asm("{ .reg .u64 t; cvta.to.shared.u64 t, %1; cvt.u32.u64 %0, t; }"
        : "=r"(a) : "l"(p));
    return a;
}
__device__ __forceinline__ uint32_t pack2(float lo, float hi) {
    __half2 h = __floats2half2_rn(lo, hi);
    return *reinterpret_cast<uint32_t*>(&h);
}
__device__ __forceinline__ void ldsm_x4(uint32_t& r0, uint32_t& r1, uint32_t& r2, uint32_t& r3,
                                        uint32_t addr) {
    asm volatile("ldmatrix.sync.aligned.m8n8.x4.shared.b16 {%0,%1,%2,%3}, [%4];"
                 : "=r"(r0), "=r"(r1), "=r"(r2), "=r"(r3) : "r"(addr));
}
__device__ __forceinline__ void ldsm_x2t(uint32_t& r0, uint32_t& r1, uint32_t addr) {
    asm volatile("ldmatrix.sync.aligned.m8n8.x2.trans.shared.b16 {%0,%1}, [%2];"
                 : "=r"(r0), "=r"(r1) : "r"(addr));
}
__device__ __forceinline__ void ldsm_x4t(uint32_t& r0, uint32_t& r1, uint32_t& r2, uint32_t& r3,
                                         uint32_t addr) {
    asm volatile("ldmatrix.sync.aligned.m8n8.x4.trans.shared.b16 {%0,%1,%2,%3}, [%4];"
                 : "=r"(r0), "=r"(r1), "=r"(r2), "=r"(r3) : "r"(addr));
}
__device__ __forceinline__ void mma16816(float* c, const uint32_t* a, uint32_t b0, uint32_t b1) {
    asm volatile("mma.sync.aligned.m16n8k16.row.col.f32.f16.f16.f32 "
                 "{%0,%1,%2,%3}, {%4,%5,%6,%7}, {%8,%9}, {%0,%1,%2,%3};"
                 : "+f"(c[0]), "+f"(c[1]), "+f"(c[2]), "+f"(c[3])
                 : "r"(a[0]), "r"(a[1]), "r"(a[2]), "r"(a[3]), "r"(b0), "r"(b1));
}
#define NAMED_BAR(id) \
    asm volatile("bar.sync %0, 128;" :: "r"(id) : "memory")

// ============================== PointNet (mma.sync f16) ==============================
// SMEM byte offsets
#define SM_W3   0        /* 128 x 512B  (f16, swizzled)  = 65536 */
#define SM_W2   65536    /* 64  x 256B                    = 16384 */
#define SM_H2   81920    /* 128 x 256B                    = 32768 */
#define SM_H1   114688   /* 128 x 128B                    = 16384 */
#define SM_B2   131072   /* 128 f32 */
#define SM_B3   131584   /* 256 f32 */
#define SM_W1   132608   /* 192 f32 */
#define SM_B1   133376   /* 64  f32 */
#define SM_TOTAL 133632

__global__ __launch_bounds__(512, 1) void pointnet_mma(
    const float* __restrict__ pts,
    const float* __restrict__ w1, const float* __restrict__ b1,
    const float* __restrict__ w2, const float* __restrict__ b2,
    const float* __restrict__ w3, const float* __restrict__ b3,
    __half* __restrict__ featp, int ntot)
{
    extern __shared__ char sm[];
    const uint32_t s0 = smem_u32(sm);
    const int tid = threadIdx.x;
    const int wid = tid >> 5, lane = tid & 31;

    // ---- Stage weights (once per block) ----
    for (int i = tid * 8; i < 128 * 256; i += 512 * 8) {
        int k = i >> 8, n = i & 255;
        float4 f0 = *reinterpret_cast<const float4*>(w3 + i);
        float4 f1 = *reinterpret_cast<const float4*>(w3 + i + 4);
        uint4 u = make_uint4(pack2(f0.x, f0.y), pack2(f0.z, f0.w),
                             pack2(f1.x, f1.y), pack2(f1.z, f1.w));
        int ch = (n >> 3) ^ (k & 7);
        *reinterpret_cast<uint4*>(sm + SM_W3 + k * 512 + ch * 16) = u;
    }
    for (int i = tid * 8; i < 64 * 128; i += 512 * 8) {
        int k = i >> 7, n = i & 127;
        float4 f0 = *reinterpret_cast<const float4*>(w2 + i);
        float4 f1 = *reinterpret_cast<const float4*>(w2 + i + 4);
        uint4 u = make_uint4(pack2(f0.x, f0.y), pack2(f0.z, f0.w),
                             pack2(f1.x, f1.y), pack2(f1.z, f1.w));
        int ch = (n >> 3) ^ (k & 7);
        *reinterpret_cast<uint4*>(sm + SM_W2 + k * 256 + ch * 16) = u;
    }
    if (tid < 128) reinterpret_cast<float*>(sm + SM_B2)[tid] = b2[tid];
    if (tid < 256) reinterpret_cast<float*>(sm + SM_B3)[tid] = b3[tid];
    if (tid < 192) reinterpret_cast<float*>(sm + SM_W1)[tid] = w1[tid];
    if (tid < 64)  reinterpret_cast<float*>(sm + SM_B1)[tid] = b1[tid];
    __syncthreads();   // only block-wide sync in the whole kernel

    const float* sW1f = reinterpret_cast<const float*>(sm + SM_W1);
    const float* sB1f = reinterpret_cast<const float*>(sm + SM_B1);
    const float* sB2f = reinterpret_cast<const float*>(sm + SM_B2);
    const float* sB3f = reinterpret_cast<const float*>(sm + SM_B3);

    const int g = lane >> 2, tig = lane & 3;
    const int rt = wid >> 2, ct = wid & 3;
    const int r0 = rt * 32;
    const int row = tid >> 2, q = tid & 3;
    const int barid = 1 + rt;           // named barrier per 4-warp group
    const int qh = lane >> 3;
    const int ql = lane & 7;

    // Prefetch first object's coords
    float nx0 = 0.f, nx1 = 0.f, nx2 = 0.f;
    if (blockIdx.x < (unsigned)ntot) {
        const float* pr = pts + (size_t)blockIdx.x * 384 + row * 3;
        nx0 = pr[0]; nx1 = pr[1]; nx2 = pr[2];
    }

    for (int obj = blockIdx.x; obj < ntot; obj += gridDim.x) {
        // ---- H1 = relu(pts@W1 + b1) -> sH1 rows [32rt, 32rt+32) ----
        {
            const float x0 = nx0, x1 = nx1, x2 = nx2;
            uint32_t u[8];
            #pragma unroll
            for (int e = 0; e < 8; e++) {
                const int c0 = q * 16 + e * 2;
                float v0 = fmaf(x2, sW1f[128 + c0],
                           fmaf(x1, sW1f[64 + c0], fmaf(x0, sW1f[c0], sB1f[c0])));
                float v1 = fmaf(x2, sW1f[129 + c0],
                           fmaf(x1, sW1f[65 + c0], fmaf(x0, sW1f[c0 + 1], sB1f[c0 + 1])));
                u[e] = pack2(fmaxf(v0, 0.f), fmaxf(v1, 0.f));
            }
            const int ch0 = (q * 2) ^ (row & 7), ch1 = (q * 2 + 1) ^ (row & 7);
            *reinterpret_cast<uint4*>(sm + SM_H1 + row * 128 + ch0 * 16) =
                make_uint4(u[0], u[1], u[2], u[3]);
            *reinterpret_cast<uint4*>(sm + SM_H1 + row * 128 + ch1 * 16) =
                make_uint4(u[4], u[5], u[6], u[7]);
            const int nobj = obj + gridDim.x;
            if (nobj < ntot) {
                const float* pr = pts + (size_t)nobj * 384 + row * 3;
                nx0 = pr[0]; nx1 = pr[1]; nx2 = pr[2];
            }
        }
        NAMED_BAR(barid);

        // ---- Phase 1: H2 rows = relu(H1 @ W2 + b2), warp tile 32x32 ----
        {
            const int n0 = ct * 32;
            uint32_t a[2][4][4];
            #pragma unroll
            for (int rg = 0; rg < 2; rg++)
                #pragma unroll
                for (int kb = 0; kb < 4; kb++) {
                    const int rr = r0 + rg * 16 + (lane & 15);
                    const int ch = (kb * 2 + (lane >> 4)) ^ (rr & 7);
                    ldsm_x4(a[rg][kb][0], a[rg][kb][1], a[rg][kb][2], a[rg][kb][3],
                            s0 + SM_H1 + rr * 128 + ch * 16);
                }
            float c[2][4][4] = {};
            #pragma unroll
            for (int kb = 0; kb < 4; kb++) {
                const int krow = kb * 16 + (qh & 1) * 8 + ql;
                #pragma unroll
                for (int jp = 0; jp < 2; jp++) {
                    const int nch = (n0 >> 3) + jp * 2 + (qh >> 1);
                    uint32_t b0, b1, b2r, b3r;
                    ldsm_x4t(b0, b1, b2r, b3r,
                             s0 + SM_W2 + krow * 256 + ((nch ^ (krow & 7)) * 16));
                    mma16816(c[0][jp * 2],     a[0][kb], b0, b1);
                    mma16816(c[1][jp * 2],     a[1][kb], b0, b1);
                    mma16816(c[0][jp * 2 + 1], a[0][kb], b2r, b3r);
                    mma16816(c[1][jp * 2 + 1], a[1][kb], b2r, b3r);
                }
            }
            #pragma unroll
            for (int rg = 0; rg < 2; rg++) {
                const int rowa = r0 + rg * 16 + g, rowb = rowa + 8;
                #pragma unroll
                for (int nb = 0; nb < 4; nb++) {
                    const int col = n0 + nb * 8 + 2 * tig;
                    const float bb0 = sB2f[col], bb1 = sB2f[col + 1];
                    const uint32_t p0 = pack2(fmaxf(c[rg][nb][0] + bb0, 0.f),
                                              fmaxf(c[rg][nb][1] + bb1, 0.f));
                    const uint32_t p1 = pack2(fmaxf(c[rg][nb][2] + bb0, 0.f),
                                              fmaxf(c[rg][nb][3] + bb1, 0.f));
                    const int nch = (n0 >> 3) + nb;
                    *reinterpret_cast<uint32_t*>(
                        sm + SM_H2 + rowa * 256 + ((nch ^ (rowa & 7)) * 16) + tig * 4) = p0;
                    *reinterpret_cast<uint32_t*>(
                        sm + SM_H2 + rowb * 256 + ((nch ^ (rowb & 7)) * 16) + tig * 4) = p1;
                }
            }
        }
        NAMED_BAR(barid);

        // ---- Phase 2: H3 = H2 @ W3; partial col-max over the group's 32 rows ----
        {
            uint32_t a[2][8][4];
            #pragma unroll
            for (int rg = 0; rg < 2; rg++)
                #pragma unroll
                for (int kb = 0; kb < 8; kb++) {
                    const int rr = r0 + rg * 16 + (lane & 15);
                    const int ch = (kb * 2 + (lane >> 4)) ^ (rr & 7);
                    ldsm_x4(a[rg][kb][0], a[rg][kb][1], a[rg][kb][2], a[rg][kb][3],
                            s0 + SM_H2 + rr * 256 + ch * 16);
                }
            __half* outp = featp + ((size_t)rt * NTOT + obj) * 256;
            #pragma unroll
            for (int tile = 0; tile < 2; tile++) {
                const int n0 = ct * 32 + tile * 128;
                float c[2][4][4] = {};
                #pragma unroll
                for (int kb = 0; kb < 8; kb++) {
                    const int krow = kb * 16 + (qh & 1) * 8 + ql;
                    #pragma unroll
                    for (int jp = 0; jp < 2; jp++) {
                        const int nch = (n0 >> 3) + jp * 2 + (qh >> 1);
                        uint32_t b0, b1, b2r, b3r;
                        ldsm_x4t(b0, b1, b2r, b3r,
                                 s0 + SM_W3 + krow * 512 + ((nch ^ (krow & 7)) * 16));
                        mma16816(c[0][jp * 2],     a[0][kb], b0, b1);
                        mma16816(c[1][jp * 2],     a[1][kb], b0, b1);
                        mma16816(c[0][jp * 2 + 1], a[0][kb], b2r, b3r);
                        mma16816(c[1][jp * 2 + 1], a[1][kb], b2r, b3r);
                    }
                }
                #pragma unroll
                for (int nb = 0; nb < 4; nb++) {
                    float m0 = fmaxf(fmaxf(c[0][nb][0], c[0][nb][2]),
                                     fmaxf(c[1][nb][0], c[1][nb][2]));
                    float m1 = fmaxf(fmaxf(c[0][nb][1], c[0][nb][3]),
                                     fmaxf(c[1][nb][1], c[1][nb][3]));
                    #pragma unroll
                    for (int off = 4; off < 32; off <<= 1) {
                        m0 = fmaxf(m0, __shfl_xor_sync(0xffffffff, m0, off));
                        m1 = fmaxf(m1, __shfl_xor_sync(0xffffffff, m1, off));
                    }
                    if (lane < 4) {
                        const int col = n0 + nb * 8 + 2 * tig;
                        __half2 hv = __floats2half2_rn(m0 + sB3f[col], m1 + sB3f[col + 1]);
                        *reinterpret_cast<__half2*>(outp + col) = hv;
                    }
                }
            }
        }
        // no block-wide sync: groups drift freely; cross-group max happens in oe_head.
    }
}

// ============================== shared GEMM building blocks ==============================
// A tile: 128 rows x 512B f16 swizzled. W tile: 256 rows x 512B.
__device__ __forceinline__ void gemm_loop_256(
    float (&c)[2][8][4], uint32_t sA0, uint32_t sW0, int r0, int n0, int lane)
{
    #pragma unroll
    for (int kb = 0; kb < 16; kb++) {
        uint32_t a[2][4];
        #pragma unroll
        for (int rg = 0; rg < 2; rg++) {
            const int rr = r0 + rg * 16 + (lane & 15);
            const int ch = (kb * 2 + (lane >> 4)) ^ (rr & 7);
            ldsm_x4(a[rg][0], a[rg][1], a[rg][2], a[rg][3], sA0 + rr * 512 + ch * 16);
        }
        const int krow = kb * 16 + (lane & 15);
        #pragma unroll
        for (int j = 0; j < 8; j++) {
            const int nch = (n0 >> 3) + j;
            uint32_t b0, b1;
            ldsm_x2t(b0, b1, sW0 + krow * 512 + ((nch ^ (krow & 7)) * 16));
            mma16816(c[0][j], a[0], b0, b1);
            mma16816(c[1][j], a[1], b0, b1);
        }
    }
}

// write (relu?)(C + bias) as f16 into sA (swizzled, rowBytes 512)
__device__ __forceinline__ void write_h_f16(
    char* sA, float (&c)[2][8][4], const float* sBias,
    int r0, int n0, int g, int tig, bool relu)
{
    #pragma unroll
    for (int rg = 0; rg < 2; rg++) {
        const int rowa = r0 + rg * 16 + g, rowb = rowa + 8;
        #pragma unroll
        for (int j = 0; j < 8; j++) {
            const int col = n0 + j * 8 + 2 * tig;
            const float bb0 = sBias[col], bb1 = sBias[col + 1];
            float v0 = c[rg][j][0] + bb0, v1 = c[rg][j][1] + bb1;
            float v2 = c[rg][j][2] + bb0, v3 = c[rg][j][3] + bb1;
            if (relu) {
                v0 = fmaxf(v0, 0.f); v1 = fmaxf(v1, 0.f);
                v2 = fmaxf(v2, 0.f); v3 = fmaxf(v3, 0.f);
            }
            const int nch = (n0 >> 3) + j;
            *reinterpret_cast<uint32_t*>(
                sA + rowa * 512 + ((nch ^ (rowa & 7)) * 16) + tig * 4) = pack2(v0, v1);
            *reinterpret_cast<uint32_t*>(
                sA + rowb * 512 + ((nch ^ (rowb & 7)) * 16) + tig * 4) = pack2(v2, v3);
        }
    }
}

__device__ __forceinline__ void stage_w256(char* sW, const float* __restrict__ W, int tid) {
    const int r = tid >> 1, h = tid & 1;
    #pragma unroll
    for (int e = 0; e < 16; e++) {
        const int c = h * 16 + e;
        float4 f0 = *reinterpret_cast<const float4*>(W + (size_t)r * 256 + c * 8);
        float4 f1 = *reinterpret_cast<const float4*>(W + (size_t)r * 256 + c * 8 + 4);
        uint4 u = make_uint4(pack2(f0.x, f0.y), pack2(f0.z, f0.w),
                             pack2(f1.x, f1.y), pack2(f1.z, f1.w));
        *reinterpret_cast<uint4*>(sW + r * 512 + ((c ^ (r & 7)) * 16)) = u;
    }
}

// stage a 256 x EMB head weight into sW (rowBytes 256, zero-padded to 128 cols)
__device__ __forceinline__ void stage_w_head(char* sW, const float* __restrict__ W, int tid) {
    const int r = tid >> 1, h = tid & 1;
    #pragma unroll
    for (int e = 0; e < 8; e++) {
        const int c = h * 8 + e;
        float v[8];
        #pragma unroll
        for (int i = 0; i < 8; i++) {
            const int col = c * 8 + i;
            v[i] = (col < EMB) ? W[(size_t)r * EMB + col] : 0.f;
        }
        uint4 u = make_uint4(pack2(v[0], v[1]), pack2(v[2], v[3]),
                             pack2(v[4], v[5]), pack2(v[6], v[7]));
        *reinterpret_cast<uint4*>(sW + r * 256 + ((c ^ (r & 7)) * 16)) = u;
    }
}

// head GEMM compute + write out (NPAD=128, wRowB=256)
__device__ __forceinline__ void head_compute(
    uint32_t sA0, uint32_t sW0, const float* sBias, float* __restrict__ out,
    int m0, int coff, int lane, int wid)
{
    const int g = lane >> 2, tig = lane & 3;
    const int rt = wid >> 2, ct = wid & 3;
    const int r0 = rt * 32;
    const int n0 = ct * 32;
    float c[2][4][4] = {};
    #pragma unroll
    for (int kb = 0; kb < 16; kb++) {
        uint32_t a[2][4];
        #pragma unroll
        for (int rg = 0; rg < 2; rg++) {
            const int rr = r0 + rg * 16 + (lane & 15);
            const int ch = (kb * 2 + (lane >> 4)) ^ (rr & 7);
            ldsm_x4(a[rg][0], a[rg][1], a[rg][2], a[rg][3], sA0 + rr * 512 + ch * 16);
        }
        const int krow = kb * 16 + (lane & 15);
        #pragma unroll
        for (int j = 0; j < 4; j++) {
            const int nch = (n0 >> 3) + j;
            uint32_t b0, b1;
            ldsm_x2t(b0, b1, sW0 + krow * 256 + ((nch ^ (krow & 7)) * 16));
            mma16816(c[0][j], a[0], b0, b1);
            mma16816(c[1][j], a[1], b0, b1);
        }
    }
    #pragma unroll
    for (int rg = 0; rg < 2; rg++) {
        const int rowa = m0 + r0 + rg * 16 + g;
        #pragma unroll
        for (int j = 0; j < 4; j++) {
            const int col = n0 + j * 8 + 2 * tig;
            const float v0 = c[rg][j][0] + sBias[col];
            const float v1 = c[rg][j][1] + sBias[col + 1];
            const float v2 = c[rg][j][2] + sBias[col];
            const float v3 = c[rg][j][3] + sBias[col + 1];
            if (col < EMB) {
                out[(size_t)rowa * 200 + coff + col] = v0;
                out[(size_t)(rowa + 8) * 200 + coff + col] = v2;
            }
            if (col + 1 < EMB) {
                out[(size_t)rowa * 200 + coff + col + 1] = v1;
                out[(size_t)(rowa + 8) * 200 + coff + col + 1] = v3;
            }
        }
    }
}

// ============================== fused sgnet: gather -> h1 -> h2 -> se head ==============================
__global__ __launch_bounds__(512) void sg_fused(
    const float* __restrict__ Asrc, const float* __restrict__ Aref,
    const float* __restrict__ w1, const float* __restrict__ b1,
    const float* __restrict__ w2, const float* __restrict__ b2,
    const float* __restrict__ sew, const float* __restrict__ seb,
    float* __restrict__ out)
{
    extern __shared__ char sm[];
    const uint32_t s0 = smem_u32(sm);
    char* sA = sm;                              // 128 x 512B
    char* sW = sm + 65536;                      // 256 x 512B
    float* sBias = reinterpret_cast<float*>(sm + 65536 + 131072);

    const int tid = threadIdx.x;
    const int wid = tid >> 5, lane = tid & 31;
    const int m0 = blockIdx.x * 128;
    const int g = lane >> 2, tig = lane & 3;
    const int rt = wid >> 2, ct = wid & 3;
    const int r0 = rt * 32;
    const int n064 = ct * 64;

    // Stage gathered A + W1 + b1
    {
        const int r = tid >> 2, q = tid & 3;
        const int m = m0 + r;
        const int b = m >> 10, j = m & 1023;
        const float* arow = (j < 512) ? (Asrc + (size_t)(b * 512 + j) * 256)
                                      : (Aref + (size_t)(b * 512 + (j - 512)) * 256);
        #pragma unroll
        for (int e = 0; e < 8; e++) {
            const int c = q * 8 + e;
            float4 f0 = *reinterpret_cast<const float4*>(arow + c * 8);
            float4 f1 = *reinterpret_cast<const float4*>(arow + c * 8 + 4);
            uint4 u = make_uint4(pack2(f0.x, f0.y), pack2(f0.z, f0.w),
                                 pack2(f1.x, f1.y), pack2(f1.z, f1.w));
            *reinterpret_cast<uint4*>(sA + r * 512 + ((c ^ (r & 7)) * 16)) = u;
        }
    }
    stage_w256(sW, w1, tid);
    if (tid < 256) sBias[tid] = b1[tid];
    __syncthreads();

    // C1 = A @ W1
    {
        float c1[2][8][4] = {};
        gemm_loop_256(c1, s0, s0 + 65536, r0, n064, lane);
        __syncthreads();                         // all reads of sA/sW done
        write_h_f16(sA, c1, sBias, r0, n064, g, tig, true);   // h1 = relu(C1+b1)
    }
    __syncthreads();                             // h1 complete; bias reads done
    stage_w256(sW, w2, tid);
    if (tid < 256) sBias[tid] = b2[tid];
    __syncthreads();

    // C2 = h1 @ W2
    {
        float c2[2][8][4] = {};
        gemm_loop_256(c2, s0, s0 + 65536, r0, n064, lane);
        __syncthreads();
        write_h_f16(sA, c2, sBias, r0, n064, g, tig, false);  // h2 = C2+b2
    }
    __syncthreads();
    stage_w_head(sW, sew, tid);
    if (tid < 128) sBias[tid] = (tid < EMB) ? seb[tid] : 0.f;
    __syncthreads();

    // out[:, 0:100] = h2 @ se_w + se_b
    head_compute(s0, s0 + 65536, sBias, out, m0, 0, lane, wid);
}

// ============================== oe head: max4(featp f16) @ oe_w + oe_b ==============================
__global__ __launch_bounds__(512) void oe_head(
    const __half* __restrict__ featp,
    const float* __restrict__ W, const float* __restrict__ bias,
    float* __restrict__ out)
{
    extern __shared__ char sm[];
    const uint32_t s0 = smem_u32(sm);
    char* sA = sm;                              // 128 x 512B
    char* sW = sm + 65536;                      // 256 x 256B
    float* sBias = reinterpret_cast<float*>(sm + 65536 + 65536);

    const int tid = threadIdx.x;
    const int wid = tid >> 5, lane = tid & 31;
    const int m0 = blockIdx.x * 128;

    // Stage A = elementwise max over the 4 partial buffers (f16)
    {
        const int r = tid >> 2, q = tid & 3;
        const int m = m0 + r;
        const __half* arow = featp + (size_t)m * 256;
        #pragma unroll
        for (int e = 0; e < 8; e++) {
            const int c = q * 8 + e;
            uint4 u = *reinterpret_cast<const uint4*>(arow + c * 8);
            __half2* uh = reinterpret_cast<__half2*>(&u);
            #pragma unroll
            for (int p = 1; p < 4; p++) {
                uint4 v = *reinterpret_cast<const uint4*>(
                    arow + (size_t)p * NTOT * 256 + c * 8);
                const __half2* vh = reinterpret_cast<const __half2*>(&v);
                uh[0] = __hmax2(uh[0], vh[0]);
                uh[1] = __hmax2(uh[1], vh[1]);
                uh[2] = __hmax2(uh[2], vh[2]);
                uh[3] = __hmax2(uh[3], vh[3]);
            }
            *reinterpret_cast<uint4*>(sA + r * 512 + ((c ^ (r & 7)) * 16)) = u;
        }
    }
    stage_w_head(sW, W, tid);
    if (tid < 128) sBias[tid] = (tid < EMB) ? bias[tid] : 0.f;
    __syncthreads();

    // out[:, 100:200] = A @ oe_w + oe_b
    head_compute(s0, s0 + 65536, sBias, out, m0, 100, lane, wid);
}

// ============================== Launch ==============================
extern "C" void kernel_launch(void* const* d_in, const int* in_sizes, int n_in,
                              void* d_out, int out_size)
{
    const float* tot_obj_pts = (const float*)d_in[0];
    const float* src_feat    = (const float*)d_in[1];
    const float* ref_feat    = (const float*)d_in[2];
    const float* sg_w1 = (const float*)d_in[6];
    const float* sg_b1 = (const float*)d_in[7];
    const float* sg_w2 = (const float*)d_in[8];
    const float* sg_b2 = (const float*)d_in[9];
    const float* se_w  = (const float*)d_in[10];
    const float* se_b  = (const float*)d_in[11];
    const float* p_w1  = (const float*)d_in[12];
    const float* p_b1  = (const float*)d_in[13];
    const float* p_w2  = (const float*)d_in[14];
    const float* p_b2  = (const float*)d_in[15];
    const float* p_w3  = (const float*)d_in[16];
    const float* p_b3  = (const float*)d_in[17];
    const float* oe_w  = (const float*)d_in[18];
    const float* oe_b  = (const float*)d_in[19];
    float* out = (float*)d_out;

    void* pfeat;
    cudaGetSymbolAddress(&pfeat, g_feat);

    int sms = 148;
    cudaDeviceGetAttribute(&sms, cudaDevAttrMultiProcessorCount, 0);

    const int SG_SMEM = 65536 + 131072 + 1024;   // 197632
    const int OE_SMEM = 65536 + 65536 + 512;     // 131584

    cudaFuncSetAttribute(pointnet_mma,
                         cudaFuncAttributeMaxDynamicSharedMemorySize, SM_TOTAL);
    cudaFuncSetAttribute(sg_fused,
                         cudaFuncAttributeMaxDynamicSharedMemorySize, SG_SMEM);
    cudaFuncSetAttribute(oe_head,
                         cudaFuncAttributeMaxDynamicSharedMemorySize, OE_SMEM);

    // PointNet (dominant, at HMMA roofline) — writes 4 f16 partial-max buffers
    pointnet_mma<<<sms, 512, SM_TOTAL>>>(
        tot_obj_pts, p_w1, p_b1, p_w2, p_b2, p_w3, p_b3, (__half*)pfeat, NTOT);

    // Fused sgnet chain: gather -> h1 -> h2 -> out[:,0:100]
    sg_fused<<<NTOT / 128, 512, SG_SMEM>>>(
        src_feat, ref_feat, sg_w1, sg_b1, sg_w2, sg_b2, se_w, se_b, out);

    // oe head: out[:,100:200] = max4(featp) @ oe_w + oe_b
    oe_head<<<NTOT / 128, 512, OE_SMEM>>>(
        (const __half*)pfeat, oe_w, oe_b, out);
}

// round 16
// speedup vs baseline: 1.1950x; 1.1452x over previous
#include <cuda_runtime.h>
#include <cuda_fp16.h>
#include <cstdint>

#define NTOT 16384
#define EMB  100

// Scratch (device globals — no runtime allocation allowed).
__device__ __half g_feat[2 * NTOT * 256]; // 2 per-group partial col-max (+b3), f16

// ============================== helpers ==============================
__device__ __forceinline__ uint32_t smem_u32(const void* p) {
    uint32_t a;
    asm("{ .reg .u64 t; cvta.to.shared.u64 t, %1; cvt.u32.u64 %0, t; }"
        : "=r"(a) : "l"(p));
    return a;
}
__device__ __forceinline__ uint32_t pack2(float lo, float hi) {
    __half2 h = __floats2half2_rn(lo, hi);
    return *reinterpret_cast<uint32_t*>(&h);
}
__device__ __forceinline__ void ldsm_x4(uint32_t& r0, uint32_t& r1, uint32_t& r2, uint32_t& r3,
                                        uint32_t addr) {
    asm volatile("ldmatrix.sync.aligned.m8n8.x4.shared.b16 {%0,%1,%2,%3}, [%4];"
                 : "=r"(r0), "=r"(r1), "=r"(r2), "=r"(r3) : "r"(addr));
}
__device__ __forceinline__ void ldsm_x2t(uint32_t& r0, uint32_t& r1, uint32_t addr) {
    asm volatile("ldmatrix.sync.aligned.m8n8.x2.trans.shared.b16 {%0,%1}, [%2];"
                 : "=r"(r0), "=r"(r1) : "r"(addr));
}
__device__ __forceinline__ void ldsm_x4t(uint32_t& r0, uint32_t& r1, uint32_t& r2, uint32_t& r3,
                                         uint32_t addr) {
    asm volatile("ldmatrix.sync.aligned.m8n8.x4.trans.shared.b16 {%0,%1,%2,%3}, [%4];"
                 : "=r"(r0), "=r"(r1), "=r"(r2), "=r"(r3) : "r"(addr));
}
__device__ __forceinline__ void mma16816(float* c, const uint32_t* a, uint32_t b0, uint32_t b1) {
    asm volatile("mma.sync.aligned.m16n8k16.row.col.f32.f16.f16.f32 "
                 "{%0,%1,%2,%3}, {%4,%5,%6,%7}, {%8,%9}, {%0,%1,%2,%3};"
                 : "+f"(c[0]), "+f"(c[1]), "+f"(c[2]), "+f"(c[3])
                 : "r"(a[0]), "r"(a[1]), "r"(a[2]), "r"(a[3]), "r"(b0), "r"(b1));
}
#define NAMED_BAR256(id) \
    asm volatile("bar.sync %0, 256;" :: "r"(id) : "memory")

// ============================== PointNet (transposed, W3 in registers) ==============================
// SMEM layout (bytes):
// [0, 16384): H1 — 2 groups × 64 pts × 128B ([pt][k=64] f16, swizzled)
// [16384, 49152): H2 — 2 groups × 128 ch × 128B ([ch][pt=64] f16, swizzled)
// [0, 65536): W3T staging ([n=256][k=128] f16, linear) — STARTUP ONLY, aliased by H1/H2
// [65536, 81920): W2T — [ch=128][k=64] f16 swizzled, rowBytes 128
// [81920..): b3, b2, w1, b1
#define SM_H1    0
#define SM_H2    16384
#define SM_W3T   0
#define SM_W2T   65536
#define SM_B3    81920
#define SM_B2    82944
#define SM_W1    83456
#define SM_B1    84224
#define SM_TOTAL 84480

__global__ __launch_bounds__(512, 1) void pointnet_mma(
    const float* __restrict__ pts,
    const float* __restrict__ w1, const float* __restrict__ b1,
    const float* __restrict__ w2, const float* __restrict__ b2,
    const float* __restrict__ w3, const float* __restrict__ b3,
    __half* __restrict__ featp, int ntot)
{
    extern __shared__ char sm[];
    const uint32_t s0 = smem_u32(sm);
    const int tid = threadIdx.x;
    const int wid = tid >> 5, lane = tid & 31;
    const int g = lane >> 2, tig = lane & 3;

    // ---- Startup staging ----
    __half* sW3T = reinterpret_cast<__half*>(sm + SM_W3T);   // [n=256][k=128]
    for (int i = tid; i < 128 * 256; i += 512) {
        int k = i >> 8, n = i & 255;
        sW3T[n * 128 + k] = __float2half_rn(w3[i]);
    }
    for (int i = tid; i < 64 * 128; i += 512) {              // W2T [ch][k], swizzled
        int k = i >> 7, n = i & 127;
        uint32_t byo = (uint32_t)(n * 128 + ((((k >> 3) ^ (n & 7)) << 4) | ((k & 7) * 2)));
        *reinterpret_cast<__half*>(sm + SM_W2T + byo) = __float2half_rn(w2[i]);
    }
    if (tid < 256) reinterpret_cast<float*>(sm + SM_B3)[tid] = b3[tid];
    if (tid < 128) reinterpret_cast<float*>(sm + SM_B2)[tid] = b2[tid];
    if (tid < 192) reinterpret_cast<float*>(sm + SM_W1)[tid] = w1[tid];
    if (tid < 64)  reinterpret_cast<float*>(sm + SM_B1)[tid] = b1[tid];
    __syncthreads();

    // ---- Persistent W3^T A-fragments (64 regs/thread) ----
    const int gamma = wid >> 3;          // group 0/1 (owns 64 points)
    const int w8 = wid & 7;
    const int c0 = w8 * 32;              // phase-2 channel base
    uint32_t aW3[2][8][4];
    #pragma unroll
    for (int mt = 0; mt < 2; mt++)
        #pragma unroll
        for (int kb = 0; kb < 8; kb++) {
            const int m = c0 + mt * 16 + g;
            const int k = kb * 16 + 2 * tig;
            aW3[mt][kb][0] = *reinterpret_cast<const uint32_t*>(&sW3T[m * 128 + k]);
            aW3[mt][kb][1] = *reinterpret_cast<const uint32_t*>(&sW3T[(m + 8) * 128 + k]);
            aW3[mt][kb][2] = *reinterpret_cast<const uint32_t*>(&sW3T[m * 128 + k + 8]);
            aW3[mt][kb][3] = *reinterpret_cast<const uint32_t*>(&sW3T[(m + 8) * 128 + k + 8]);
        }
    __syncthreads();    // W3T staging region now free (aliased by H1/H2)

    char* h1gp = sm + SM_H1 + gamma * 8192;
    char* h2gp = sm + SM_H2 + gamma * 16384;
    const uint32_t h1g = s0 + SM_H1 + gamma * 8192;
    const uint32_t h2g = s0 + SM_H2 + gamma * 16384;
    const int barid = 1 + gamma;
    const int t = tid & 255;
    const int row = t >> 2, q = t & 3;               // H1 stage mapping (64 rows/group)
    const int p1m0 = (w8 & 3) * 32;                  // phase-1 channel tile
    const int p1n0 = (w8 >> 2) * 32;                 // phase-1 point tile
    const float* sW1f = reinterpret_cast<const float*>(sm + SM_W1);
    const float* sB1f = reinterpret_cast<const float*>(sm + SM_B1);
    const float* sB2f = reinterpret_cast<const float*>(sm + SM_B2);
    const float* sB3f = reinterpret_cast<const float*>(sm + SM_B3);
    // phase-1 B address components (non-trans x4 from H1[pt][k])
    const int bo = (lane >> 4) & 1, bh = (lane >> 3) & 1, br = lane & 7;

    // Prefetch first object's coords (this group's 64 points)
    float nx0 = 0.f, nx1 = 0.f, nx2 = 0.f;
    if (blockIdx.x < (unsigned)ntot) {
        const float* pr = pts + (size_t)blockIdx.x * 384 + (gamma * 64 + row) * 3;
        nx0 = pr[0]; nx1 = pr[1]; nx2 = pr[2];
    }

    for (int obj = blockIdx.x; obj < ntot; obj += gridDim.x) {
        // ---- H1[pt][64] = relu(pts@W1 + b1), f16 swizzled ----
        {
            const float x0 = nx0, x1 = nx1, x2 = nx2;
            uint32_t u[8];
            #pragma unroll
            for (int e4 = 0; e4 < 4; e4++) {
                const int cb = q * 16 + e4 * 4;
                const float4 wx = *reinterpret_cast<const float4*>(&sW1f[cb]);
                const float4 wy = *reinterpret_cast<const float4*>(&sW1f[64 + cb]);
                const float4 wz = *reinterpret_cast<const float4*>(&sW1f[128 + cb]);
                const float4 bb = *reinterpret_cast<const float4*>(&sB1f[cb]);
                const float v0 = fmaf(x2, wz.x, fmaf(x1, wy.x, fmaf(x0, wx.x, bb.x)));
                const float v1 = fmaf(x2, wz.y, fmaf(x1, wy.y, fmaf(x0, wx.y, bb.y)));
                const float v2 = fmaf(x2, wz.z, fmaf(x1, wy.z, fmaf(x0, wx.z, bb.z)));
                const float v3 = fmaf(x2, wz.w, fmaf(x1, wy.w, fmaf(x0, wx.w, bb.w)));
                u[e4 * 2]     = pack2(fmaxf(v0, 0.f), fmaxf(v1, 0.f));
                u[e4 * 2 + 1] = pack2(fmaxf(v2, 0.f), fmaxf(v3, 0.f));
            }
            const int ch0 = (q * 2) ^ (row & 7), ch1 = (q * 2 + 1) ^ (row & 7);
            *reinterpret_cast<uint4*>(h1gp + row * 128 + ch0 * 16) =
                make_uint4(u[0], u[1], u[2], u[3]);
            *reinterpret_cast<uint4*>(h1gp + row * 128 + ch1 * 16) =
                make_uint4(u[4], u[5], u[6], u[7]);
            const int nobj = obj + gridDim.x;
            if (nobj < ntot) {
                const float* pr = pts + (size_t)nobj * 384 + (gamma * 64 + row) * 3;
                nx0 = pr[0]; nx1 = pr[1]; nx2 = pr[2];
            }
        }
        NAMED_BAR256(barid);

        // ---- Phase 1 (transposed): H2[ch][pt] = relu(W2^T @ H1^T + b2) ----
        // warp tile: 32 channels x 32 points (two point-halves of 16)
        #pragma unroll
        for (int nh = 0; nh < 2; nh++) {
            const int n0h = p1n0 + nh * 16;
            float acc[2][2][4] = {};
            #pragma unroll
            for (int kb = 0; kb < 4; kb++) {
                uint32_t a[2][4];
                #pragma unroll
                for (int mt = 0; mt < 2; mt++) {
                    const int rr = p1m0 + mt * 16 + (lane & 15);
                    const int chn = (kb * 2 + (lane >> 4)) ^ (rr & 7);
                    ldsm_x4(a[mt][0], a[mt][1], a[mt][2], a[mt][3],
                            s0 + SM_W2T + rr * 128 + chn * 16);
                }
                uint32_t b0, b1, b2r, b3r;
                {
                    const int prow = n0h + bo * 8 + br;
                    const int chn = (kb * 2 + bh) ^ (prow & 7);
                    ldsm_x4(b0, b1, b2r, b3r, h1g + prow * 128 + chn * 16);
                }
                #pragma unroll
                for (int mt = 0; mt < 2; mt++) {
                    mma16816(acc[mt][0], a[mt], b0, b1);
                    mma16816(acc[mt][1], a[mt], b2r, b3r);
                }
            }
            // epilogue: +b2 (per channel row), relu, STS to H2[ch][pt]
            #pragma unroll
            for (int mt = 0; mt < 2; mt++) {
                const int cha = p1m0 + mt * 16 + g, chb = cha + 8;
                const float ba = sB2f[cha], bbv = sB2f[chb];
                #pragma unroll
                for (int oc = 0; oc < 2; oc++) {
                    const int ptch = ((n0h + oc * 8) >> 3);
                    const uint32_t p0 = pack2(fmaxf(acc[mt][oc][0] + ba, 0.f),
                                              fmaxf(acc[mt][oc][1] + ba, 0.f));
                    const uint32_t p1 = pack2(fmaxf(acc[mt][oc][2] + bbv, 0.f),
                                              fmaxf(acc[mt][oc][3] + bbv, 0.f));
                    *reinterpret_cast<uint32_t*>(
                        h2gp + cha * 128 + ((ptch ^ (cha & 7)) << 4) + tig * 4) = p0;
                    *reinterpret_cast<uint32_t*>(
                        h2gp + chb * 128 + ((ptch ^ (chb & 7)) << 4) + tig * 4) = p1;
                }
            }
        }
        NAMED_BAR256(barid);

        // ---- Phase 2 (transposed): H3^T = W3^T(regs) @ H2^T; max over points ----
        {
            float rm[2][2] = {{-3.4e38f, -3.4e38f}, {-3.4e38f, -3.4e38f}};
            #pragma unroll
            for (int ptc = 0; ptc < 4; ptc++) {       // 4 chunks of 16 points
                float acc[2][2][4] = {};
                #pragma unroll
                for (int kb = 0; kb < 8; kb++) {
                    const int qh = lane >> 3, ql = lane & 7;
                    const int krow = kb * 16 + (qh & 1) * 8 + ql;
                    const int chn = (ptc * 2 + (qh >> 1)) ^ (krow & 7);
                    uint32_t b0, b1, b2r, b3r;
                    ldsm_x4t(b0, b1, b2r, b3r, h2g + krow * 128 + chn * 16);
                    #pragma unroll
                    for (int mt = 0; mt < 2; mt++) {
                        mma16816(acc[mt][0], aW3[mt][kb], b0, b1);
                        mma16816(acc[mt][1], aW3[mt][kb], b2r, b3r);
                    }
                }
                #pragma unroll
                for (int mt = 0; mt < 2; mt++)
                    #pragma unroll
                    for (int oc = 0; oc < 2; oc++) {
                        rm[mt][0] = fmaxf(rm[mt][0], fmaxf(acc[mt][oc][0], acc[mt][oc][1]));
                        rm[mt][1] = fmaxf(rm[mt][1], fmaxf(acc[mt][oc][2], acc[mt][oc][3]));
                    }
            }
            // reduce over the 4 tig lanes (point positions), then store
            #pragma unroll
            for (int mt = 0; mt < 2; mt++)
                #pragma unroll
                for (int rh = 0; rh < 2; rh++) {
                    float v = rm[mt][rh];
                    v = fmaxf(v, __shfl_xor_sync(0xffffffff, v, 1));
                    v = fmaxf(v, __shfl_xor_sync(0xffffffff, v, 2));
                    rm[mt][rh] = v;
                }
            __half* outp = featp + ((size_t)gamma * NTOT + obj) * 256;
            #pragma unroll
            for (int mt = 0; mt < 2; mt++)
                #pragma unroll
                for (int rh = 0; rh < 2; rh++)
                    if (tig == mt * 2 + rh) {
                        const int ch = c0 + mt * 16 + rh * 8 + g;
                        outp[ch] = __float2half_rn(rm[mt][rh] + sB3f[ch]);
                    }
        }
        // no block-wide sync: groups drift freely; cross-group max in oe_head.
    }
}

// ============================== shared GEMM building blocks (sgnet) ==============================
__device__ __forceinline__ void gemm_loop_256(
    float (&c)[2][8][4], uint32_t sA0, uint32_t sW0, int r0, int n0, int lane)
{
    #pragma unroll
    for (int kb = 0; kb < 16; kb++) {
        uint32_t a[2][4];
        #pragma unroll
        for (int rg = 0; rg < 2; rg++) {
            const int rr = r0 + rg * 16 + (lane & 15);
            const int ch = (kb * 2 + (lane >> 4)) ^ (rr & 7);
            ldsm_x4(a[rg][0], a[rg][1], a[rg][2], a[rg][3], sA0 + rr * 512 + ch * 16);
        }
        const int krow = kb * 16 + (lane & 15);
        #pragma unroll
        for (int j = 0; j < 8; j++) {
            const int nch = (n0 >> 3) + j;
            uint32_t b0, b1;
            ldsm_x2t(b0, b1, sW0 + krow * 512 + ((nch ^ (krow & 7)) * 16));
            mma16816(c[0][j], a[0], b0, b1);
            mma16816(c[1][j], a[1], b0, b1);
        }
    }
}

__device__ __forceinline__ void write_h_f16(
    char* sA, float (&c)[2][8][4], const float* sBias,
    int r0, int n0, int g, int tig, bool relu)
{
    #pragma unroll
    for (int rg = 0; rg < 2; rg++) {
        const int rowa = r0 + rg * 16 + g, rowb = rowa + 8;
        #pragma unroll
        for (int j = 0; j < 8; j++) {
            const int col = n0 + j * 8 + 2 * tig;
            const float bb0 = sBias[col], bb1 = sBias[col + 1];
            float v0 = c[rg][j][0] + bb0, v1 = c[rg][j][1] + bb1;
            float v2 = c[rg][j][2] + bb0, v3 = c[rg][j][3] + bb1;
            if (relu) {
                v0 = fmaxf(v0, 0.f); v1 = fmaxf(v1, 0.f);
                v2 = fmaxf(v2, 0.f); v3 = fmaxf(v3, 0.f);
            }
            const int nch = (n0 >> 3) + j;
            *reinterpret_cast<uint32_t*>(
                sA + rowa * 512 + ((nch ^ (rowa & 7)) * 16) + tig * 4) = pack2(v0, v1);
            *reinterpret_cast<uint32_t*>(
                sA + rowb * 512 + ((nch ^ (rowb & 7)) * 16) + tig * 4) = pack2(v2, v3);
        }
    }
}

__device__ __forceinline__ void stage_w256(char* sW, const float* __restrict__ W, int tid) {
    const int r = tid >> 1, h = tid & 1;
    #pragma unroll
    for (int e = 0; e < 16; e++) {
        const int c = h * 16 + e;
        float4 f0 = *reinterpret_cast<const float4*>(W + (size_t)r * 256 + c * 8);
        float4 f1 = *reinterpret_cast<const float4*>(W + (size_t)r * 256 + c * 8 + 4);
        uint4 u = make_uint4(pack2(f0.x, f0.y), pack2(f0.z, f0.w),
                             pack2(f1.x, f1.y), pack2(f1.z, f1.w));
        *reinterpret_cast<uint4*>(sW + r * 512 + ((c ^ (r & 7)) * 16)) = u;
    }
}

__device__ __forceinline__ void stage_w_head(char* sW, const float* __restrict__ W, int tid) {
    const int r = tid >> 1, h = tid & 1;
    #pragma unroll
    for (int e = 0; e < 8; e++) {
        const int c = h * 8 + e;
        float v[8];
        #pragma unroll
        for (int i = 0; i < 8; i++) {
            const int col = c * 8 + i;
            v[i] = (col < EMB) ? W[(size_t)r * EMB + col] : 0.f;
        }
        uint4 u = make_uint4(pack2(v[0], v[1]), pack2(v[2], v[3]),
                             pack2(v[4], v[5]), pack2(v[6], v[7]));
        *reinterpret_cast<uint4*>(sW + r * 256 + ((c ^ (r & 7)) * 16)) = u;
    }
}

__device__ __forceinline__ void head_compute(
    uint32_t sA0, uint32_t sW0, const float* sBias, float* __restrict__ out,
    int m0, int coff, int lane, int wid)
{
    const int g = lane >> 2, tig = lane & 3;
    const int rt = wid >> 2, ct = wid & 3;
    const int r0 = rt * 32;
    const int n0 = ct * 32;
    float c[2][4][4] = {};
    #pragma unroll
    for (int kb = 0; kb < 16; kb++) {
        uint32_t a[2][4];
        #pragma unroll
        for (int rg = 0; rg < 2; rg++) {
            const int rr = r0 + rg * 16 + (lane & 15);
            const int ch = (kb * 2 + (lane >> 4)) ^ (rr & 7);
            ldsm_x4(a[rg][0], a[rg][1], a[rg][2], a[rg][3], sA0 + rr * 512 + ch * 16);
        }
        const int krow = kb * 16 + (lane & 15);
        #pragma unroll
        for (int j = 0; j < 4; j++) {
            const int nch = (n0 >> 3) + j;
            uint32_t b0, b1;
            ldsm_x2t(b0, b1, sW0 + krow * 256 + ((nch ^ (krow & 7)) * 16));
            mma16816(c[0][j], a[0], b0, b1);
            mma16816(c[1][j], a[1], b0, b1);
        }
    }
    #pragma unroll
    for (int rg = 0; rg < 2; rg++) {
        const int rowa = m0 + r0 + rg * 16 + g;
        #pragma unroll
        for (int j = 0; j < 4; j++) {
            const int col = n0 + j * 8 + 2 * tig;
            const float v0 = c[rg][j][0] + sBias[col];
            const float v1 = c[rg][j][1] + sBias[col + 1];
            const float v2 = c[rg][j][2] + sBias[col];
            const float v3 = c[rg][j][3] + sBias[col + 1];
            if (col < EMB) {
                out[(size_t)rowa * 200 + coff + col] = v0;
                out[(size_t)(rowa + 8) * 200 + coff + col] = v2;
            }
            if (col + 1 < EMB) {
                out[(size_t)rowa * 200 + coff + col + 1] = v1;
                out[(size_t)(rowa + 8) * 200 + coff + col + 1] = v3;
            }
        }
    }
}

// ============================== fused sgnet: gather -> h1 -> h2 -> se head ==============================
__global__ __launch_bounds__(512) void sg_fused(
    const float* __restrict__ Asrc, const float* __restrict__ Aref,
    const float* __restrict__ w1, const float* __restrict__ b1,
    const float* __restrict__ w2, const float* __restrict__ b2,
    const float* __restrict__ sew, const float* __restrict__ seb,
    float* __restrict__ out)
{
    extern __shared__ char sm[];
    const uint32_t s0 = smem_u32(sm);
    char* sA = sm;                              // 128 x 512B
    char* sW = sm + 65536;                      // 256 x 512B
    float* sBias = reinterpret_cast<float*>(sm + 65536 + 131072);

    const int tid = threadIdx.x;
    const int wid = tid >> 5, lane = tid & 31;
    const int m0 = blockIdx.x * 128;
    const int g = lane >> 2, tig = lane & 3;
    const int rt = wid >> 2, ct = wid & 3;
    const int r0 = rt * 32;
    const int n064 = ct * 64;

    {
        const int r = tid >> 2, q = tid & 3;
        const int m = m0 + r;
        const int b = m >> 10, j = m & 1023;
        const float* arow = (j < 512) ? (Asrc + (size_t)(b * 512 + j) * 256)
                                      : (Aref + (size_t)(b * 512 + (j - 512)) * 256);
        #pragma unroll
        for (int e = 0; e < 8; e++) {
            const int c = q * 8 + e;
            float4 f0 = *reinterpret_cast<const float4*>(arow + c * 8);
            float4 f1 = *reinterpret_cast<const float4*>(arow + c * 8 + 4);
            uint4 u = make_uint4(pack2(f0.x, f0.y), pack2(f0.z, f0.w),
                                 pack2(f1.x, f1.y), pack2(f1.z, f1.w));
            *reinterpret_cast<uint4*>(sA + r * 512 + ((c ^ (r & 7)) * 16)) = u;
        }
    }
    stage_w256(sW, w1, tid);
    if (tid < 256) sBias[tid] = b1[tid];
    __syncthreads();

    {
        float c1[2][8][4] = {};
        gemm_loop_256(c1, s0, s0 + 65536, r0, n064, lane);
        __syncthreads();
        write_h_f16(sA, c1, sBias, r0, n064, g, tig, true);
    }
    __syncthreads();
    stage_w256(sW, w2, tid);
    if (tid < 256) sBias[tid] = b2[tid];
    __syncthreads();

    {
        float c2[2][8][4] = {};
        gemm_loop_256(c2, s0, s0 + 65536, r0, n064, lane);
        __syncthreads();
        write_h_f16(sA, c2, sBias, r0, n064, g, tig, false);
    }
    __syncthreads();
    stage_w_head(sW, sew, tid);
    if (tid < 128) sBias[tid] = (tid < EMB) ? seb[tid] : 0.f;
    __syncthreads();

    head_compute(s0, s0 + 65536, sBias, out, m0, 0, lane, wid);
}

// ============================== oe head: max2(featp f16) @ oe_w + oe_b ==============================
__global__ __launch_bounds__(512) void oe_head(
    const __half* __restrict__ featp,
    const float* __restrict__ W, const float* __restrict__ bias,
    float* __restrict__ out)
{
    extern __shared__ char sm[];
    const uint32_t s0 = smem_u32(sm);
    char* sA = sm;                              // 128 x 512B
    char* sW = sm + 65536;                      // 256 x 256B
    float* sBias = reinterpret_cast<float*>(sm + 65536 + 65536);

    const int tid = threadIdx.x;
    const int wid = tid >> 5, lane = tid & 31;
    const int m0 = blockIdx.x * 128;

    {
        const int r = tid >> 2, q = tid & 3;
        const int m = m0 + r;
        const __half* arow = featp + (size_t)m * 256;
        #pragma unroll
        for (int e = 0; e < 8; e++) {
            const int c = q * 8 + e;
            uint4 u = *reinterpret_cast<const uint4*>(arow + c * 8);
            uint4 v = *reinterpret_cast<const uint4*>(arow + (size_t)NTOT * 256 + c * 8);
            __half2* uh = reinterpret_cast<__half2*>(&u);
            const __half2* vh = reinterpret_cast<const __half2*>(&v);
            uh[0] = __hmax2(uh[0], vh[0]);
            uh[1] = __hmax2(uh[1], vh[1]);
            uh[2] = __hmax2(uh[2], vh[2]);
            uh[3] = __hmax2(uh[3], vh[3]);
            *reinterpret_cast<uint4*>(sA + r * 512 + ((c ^ (r & 7)) * 16)) = u;
        }
    }
    stage_w_head(sW, W, tid);
    if (tid < 128) sBias[tid] = (tid < EMB) ? bias[tid] : 0.f;
    __syncthreads();

    head_compute(s0, s0 + 65536, sBias, out, m0, 100, lane, wid);
}

// ============================== Launch ==============================
extern "C" void kernel_launch(void* const* d_in, const int* in_sizes, int n_in,
                              void* d_out, int out_size)
{
    const float* tot_obj_pts = (const float*)d_in[0];
    const float* src_feat    = (const float*)d_in[1];
    const float* ref_feat    = (const float*)d_in[2];
    const float* sg_w1 = (const float*)d_in[6];
    const float* sg_b1 = (const float*)d_in[7];
    const float* sg_w2 = (const float*)d_in[8];
    const float* sg_b2 = (const float*)d_in[9];
    const float* se_w  = (const float*)d_in[10];
    const float* se_b  = (const float*)d_in[11];
    const float* p_w1  = (const float*)d_in[12];
    const float* p_b1  = (const float*)d_in[13];
    const float* p_w2  = (const float*)d_in[14];
    const float* p_b2  = (const float*)d_in[15];
    const float* p_w3  = (const float*)d_in[16];
    const float* p_b3  = (const float*)d_in[17];
    const float* oe_w  = (const float*)d_in[18];
    const float* oe_b  = (const float*)d_in[19];
    float* out = (float*)d_out;

    void* pfeat;
    cudaGetSymbolAddress(&pfeat, g_feat);

    int sms = 148;
    cudaDeviceGetAttribute(&sms, cudaDevAttrMultiProcessorCount, 0);

    const int SG_SMEM = 65536 + 131072 + 1024;   // 197632
    const int OE_SMEM = 65536 + 65536 + 512;     // 131584

    cudaFuncSetAttribute(pointnet_mma,
                         cudaFuncAttributeMaxDynamicSharedMemorySize, SM_TOTAL);
    cudaFuncSetAttribute(sg_fused,
                         cudaFuncAttributeMaxDynamicSharedMemorySize, SG_SMEM);
    cudaFuncSetAttribute(oe_head,
                         cudaFuncAttributeMaxDynamicSharedMemorySize, OE_SMEM);

    // PointNet (dominant) — transposed GEMMs, W3 register-resident
    pointnet_mma<<<sms, 512, SM_TOTAL>>>(
        tot_obj_pts, p_w1, p_b1, p_w2, p_b2, p_w3, p_b3, (__half*)pfeat, NTOT);

    // Fused sgnet chain: gather -> h1 -> h2 -> out[:,0:100]
    sg_fused<<<NTOT / 128, 512, SG_SMEM>>>(
        src_feat, ref_feat, sg_w1, sg_b1, sg_w2, sg_b2, se_w, se_b, out);

    // oe head: out[:,100:200] = max2(featp) @ oe_w + oe_b
    oe_head<<<NTOT / 128, 512, OE_SMEM>>>(
        (const __half*)pfeat, oe_w, oe_b, out);
}